// round 1
// baseline (speedup 1.0000x reference)
#include <cuda_runtime.h>
#include <math.h>

#define D_MODEL 1024
#define D_FF    4096
#define N_HEADS 16
#define D_HEAD  64
#define BATCH   2
#define SEQ     2048
#define NROWS   (BATCH*SEQ)   /* 4096 */

// ---------------- scratch (device globals; no allocation allowed) ----------
__device__ float g_h  [NROWS * D_MODEL];
__device__ float g_q  [NROWS * D_MODEL];
__device__ float g_k  [NROWS * D_MODEL];
__device__ float g_v  [NROWS * D_MODEL];
__device__ float g_at [NROWS * D_MODEL];
__device__ float g_x1 [NROWS * D_MODEL];
__device__ float g_h2 [NROWS * D_MODEL];
__device__ float g_ff [NROWS * D_FF];

// ---------------- layernorm: one block per row (1024 elems) ----------------
__global__ __launch_bounds__(256) void ln_kernel(const float* __restrict__ x,
        const float* __restrict__ g, const float* __restrict__ b,
        float* __restrict__ out)
{
    __shared__ float red[256];
    const int row = blockIdx.x, t = threadIdx.x;
    const float4* xr = reinterpret_cast<const float4*>(x + (size_t)row * D_MODEL);
    float4 v = xr[t];
    red[t] = v.x + v.y + v.z + v.w;
    __syncthreads();
    #pragma unroll
    for (int o = 128; o > 0; o >>= 1) { if (t < o) red[t] += red[t + o]; __syncthreads(); }
    const float mu = red[0] * (1.0f / D_MODEL);
    __syncthreads();
    const float dx = v.x - mu, dy = v.y - mu, dz = v.z - mu, dw = v.w - mu;
    red[t] = dx*dx + dy*dy + dz*dz + dw*dw;
    __syncthreads();
    #pragma unroll
    for (int o = 128; o > 0; o >>= 1) { if (t < o) red[t] += red[t + o]; __syncthreads(); }
    const float rs = rsqrtf(red[0] * (1.0f / D_MODEL) + 1e-5f);
    const float4 gv = reinterpret_cast<const float4*>(g)[t];
    const float4 bv = reinterpret_cast<const float4*>(b)[t];
    float4 o4 = make_float4(dx*rs*gv.x + bv.x, dy*rs*gv.y + bv.y,
                            dz*rs*gv.z + bv.z, dw*rs*gv.w + bv.w);
    reinterpret_cast<float4*>(out + (size_t)row * D_MODEL)[t] = o4;
}

// ---------------- SGEMM: C[M,N] = A[M,K] * B[N,K]^T (+epilogue) ------------
// EPI: 0 = none, 1 = +res, 2 = gelu(.+bias), 3 = +bias+res
__device__ __forceinline__ float gelu_exact(float v)
{
    return 0.5f * v * (1.0f + erff(v * 0.70710678118654752f));
}

template<int EPI>
__global__ __launch_bounds__(256) void gemm_nt(const float* __restrict__ A,
        const float* __restrict__ B, const float* __restrict__ bias,
        const float* __restrict__ res, float* __restrict__ C,
        int M, int N, int K)
{
    __shared__ float As[8][128];
    __shared__ float Bs[8][128];
    const int t  = threadIdx.x;
    const int tx = t & 15, ty = t >> 4;
    const int rowB = blockIdx.y * 128, colB = blockIdx.x * 128;
    const int lr = t >> 1;            // 0..127
    const int lk = (t & 1) * 4;       // 0 or 4
    const float* Ap = A + (size_t)(rowB + lr) * K + lk;
    const float* Bp = B + (size_t)(colB + lr) * K + lk;

    float acc[8][8];
    #pragma unroll
    for (int i = 0; i < 8; i++)
        #pragma unroll
        for (int j = 0; j < 8; j++) acc[i][j] = 0.0f;

    for (int k0 = 0; k0 < K; k0 += 8) {
        float4 av = *reinterpret_cast<const float4*>(Ap + k0);
        float4 bv = *reinterpret_cast<const float4*>(Bp + k0);
        As[lk+0][lr] = av.x; As[lk+1][lr] = av.y; As[lk+2][lr] = av.z; As[lk+3][lr] = av.w;
        Bs[lk+0][lr] = bv.x; Bs[lk+1][lr] = bv.y; Bs[lk+2][lr] = bv.z; Bs[lk+3][lr] = bv.w;
        __syncthreads();
        #pragma unroll
        for (int kk = 0; kk < 8; kk++) {
            float4 a0 = *reinterpret_cast<const float4*>(&As[kk][ty*4]);
            float4 a1 = *reinterpret_cast<const float4*>(&As[kk][64 + ty*4]);
            float4 b0 = *reinterpret_cast<const float4*>(&Bs[kk][tx*4]);
            float4 b1 = *reinterpret_cast<const float4*>(&Bs[kk][64 + tx*4]);
            float af[8] = {a0.x,a0.y,a0.z,a0.w,a1.x,a1.y,a1.z,a1.w};
            float bf[8] = {b0.x,b0.y,b0.z,b0.w,b1.x,b1.y,b1.z,b1.w};
            #pragma unroll
            for (int i = 0; i < 8; i++)
                #pragma unroll
                for (int j = 0; j < 8; j++)
                    acc[i][j] = fmaf(af[i], bf[j], acc[i][j]);
        }
        __syncthreads();
    }

    #pragma unroll
    for (int i = 0; i < 8; i++) {
        const int r = rowB + (i < 4 ? ty*4 + i : 64 + ty*4 + (i - 4));
        #pragma unroll
        for (int j = 0; j < 8; j++) {
            const int c = colB + (j < 4 ? tx*4 + j : 64 + tx*4 + (j - 4));
            float v = acc[i][j];
            if (EPI == 1) v += res[(size_t)r * N + c];
            if (EPI == 2) v = gelu_exact(v + bias[c]);
            if (EPI == 3) v += bias[c] + res[(size_t)r * N + c];
            C[(size_t)r * N + c] = v;
        }
    }
}

// ---------------- flash attention: BQ=64, BK=32, d_head=64 -----------------
__global__ __launch_bounds__(256) void flash_kernel(const float* __restrict__ Q,
        const float* __restrict__ Km, const float* __restrict__ V,
        float* __restrict__ O)
{
    __shared__ float QsT[64][68];   // [d][q], float4-aligned rows
    __shared__ float KsT[64][34];   // [d][k], float2-aligned rows
    __shared__ float Vs [32][68];   // [k][d]
    __shared__ float PsT[32][68];   // [k][q]
    const int t  = threadIdx.x;
    const int tx = t & 15, ty = t >> 4;
    const int bh = blockIdx.y;                     // 0..31
    const size_t base = (size_t)(bh >> 4) * SEQ * D_MODEL + (size_t)(bh & 15) * D_HEAD;
    const int qb = blockIdx.x * 64;

    // load + transpose + pre-scale Q tile (64 q x 64 d)
    #pragma unroll
    for (int i = 0; i < 4; i++) {
        const int lin = i * 256 + t;
        const int row = lin >> 4, d = (lin & 15) * 4;
        float4 v = *reinterpret_cast<const float4*>(Q + base + (size_t)(qb + row) * D_MODEL + d);
        QsT[d+0][row] = v.x * 0.125f;
        QsT[d+1][row] = v.y * 0.125f;
        QsT[d+2][row] = v.z * 0.125f;
        QsT[d+3][row] = v.w * 0.125f;
    }

    float m[4], l[4], o[4][4];
    #pragma unroll
    for (int i = 0; i < 4; i++) {
        m[i] = -1e30f; l[i] = 0.0f;
        #pragma unroll
        for (int j = 0; j < 4; j++) o[i][j] = 0.0f;
    }

    for (int kt = 0; kt < SEQ; kt += 32) {
        __syncthreads();   // previous iter's consumers of KsT/Vs/PsT are done
        #pragma unroll
        for (int i = 0; i < 2; i++) {
            const int lin = i * 256 + t;
            const int row = lin >> 4, d = (lin & 15) * 4;
            const size_t goff = base + (size_t)(kt + row) * D_MODEL + d;
            float4 kv = *reinterpret_cast<const float4*>(Km + goff);
            KsT[d+0][row] = kv.x; KsT[d+1][row] = kv.y;
            KsT[d+2][row] = kv.z; KsT[d+3][row] = kv.w;
            float4 vv = *reinterpret_cast<const float4*>(V + goff);
            *reinterpret_cast<float4*>(&Vs[row][d]) = vv;
        }
        __syncthreads();

        // S tile: 4 q-rows (ty*4+) x 2 k-cols (tx*2+)
        float s[4][2] = {};
        #pragma unroll 8
        for (int kd = 0; kd < 64; kd++) {
            float4 qv = *reinterpret_cast<const float4*>(&QsT[kd][ty*4]);
            float2 kv = *reinterpret_cast<const float2*>(&KsT[kd][tx*2]);
            s[0][0] = fmaf(qv.x, kv.x, s[0][0]); s[0][1] = fmaf(qv.x, kv.y, s[0][1]);
            s[1][0] = fmaf(qv.y, kv.x, s[1][0]); s[1][1] = fmaf(qv.y, kv.y, s[1][1]);
            s[2][0] = fmaf(qv.z, kv.x, s[2][0]); s[2][1] = fmaf(qv.z, kv.y, s[2][1]);
            s[3][0] = fmaf(qv.w, kv.x, s[3][0]); s[3][1] = fmaf(qv.w, kv.y, s[3][1]);
        }

        // online softmax per row (reduce over the 16 lanes that share ty)
        #pragma unroll
        for (int i = 0; i < 4; i++) {
            float mx = fmaxf(s[i][0], s[i][1]);
            #pragma unroll
            for (int off = 8; off > 0; off >>= 1)
                mx = fmaxf(mx, __shfl_xor_sync(0xffffffffu, mx, off));
            const float mn   = fmaxf(m[i], mx);
            const float corr = __expf(m[i] - mn);
            const float p0 = __expf(s[i][0] - mn);
            const float p1 = __expf(s[i][1] - mn);
            float sm = p0 + p1;
            #pragma unroll
            for (int off = 8; off > 0; off >>= 1)
                sm += __shfl_xor_sync(0xffffffffu, sm, off);
            l[i] = l[i] * corr + sm;
            m[i] = mn;
            o[i][0] *= corr; o[i][1] *= corr; o[i][2] *= corr; o[i][3] *= corr;
            PsT[tx*2 + 0][ty*4 + i] = p0;
            PsT[tx*2 + 1][ty*4 + i] = p1;
        }
        __syncthreads();

        // O accumulate: 4 q-rows x 4 dims (tx*4+)
        #pragma unroll 4
        for (int j = 0; j < 32; j++) {
            float4 p4 = *reinterpret_cast<const float4*>(&PsT[j][ty*4]);
            float4 v4 = *reinterpret_cast<const float4*>(&Vs[j][tx*4]);
            float pj[4] = {p4.x, p4.y, p4.z, p4.w};
            float vj[4] = {v4.x, v4.y, v4.z, v4.w};
            #pragma unroll
            for (int i = 0; i < 4; i++)
                #pragma unroll
                for (int d = 0; d < 4; d++)
                    o[i][d] = fmaf(pj[i], vj[d], o[i][d]);
        }
    }

    #pragma unroll
    for (int i = 0; i < 4; i++) {
        const float inv = 1.0f / l[i];
        float4 o4 = make_float4(o[i][0]*inv, o[i][1]*inv, o[i][2]*inv, o[i][3]*inv);
        *reinterpret_cast<float4*>(O + base + (size_t)(qb + ty*4 + i) * D_MODEL + tx*4) = o4;
    }
}

// ---------------- launch --------------------------------------------------
extern "C" void kernel_launch(void* const* d_in, const int* in_sizes, int n_in,
                              void* d_out, int out_size)
{
    const float* x    = (const float*)d_in[0];
    const float* wq   = (const float*)d_in[1];
    const float* wk   = (const float*)d_in[2];
    const float* wv   = (const float*)d_in[3];
    const float* wo   = (const float*)d_in[4];
    const float* w1   = (const float*)d_in[5];
    const float* b1   = (const float*)d_in[6];
    const float* w2   = (const float*)d_in[7];
    const float* b2   = (const float*)d_in[8];
    const float* ln1g = (const float*)d_in[9];
    const float* ln1b = (const float*)d_in[10];
    const float* ln2g = (const float*)d_in[11];
    const float* ln2b = (const float*)d_in[12];
    float* out = (float*)d_out;

    float *h, *q, *k, *v, *at, *x1, *h2, *ff;
    cudaGetSymbolAddress((void**)&h,  g_h);
    cudaGetSymbolAddress((void**)&q,  g_q);
    cudaGetSymbolAddress((void**)&k,  g_k);
    cudaGetSymbolAddress((void**)&v,  g_v);
    cudaGetSymbolAddress((void**)&at, g_at);
    cudaGetSymbolAddress((void**)&x1, g_x1);
    cudaGetSymbolAddress((void**)&h2, g_h2);
    cudaGetSymbolAddress((void**)&ff, g_ff);

    const dim3 blk(256);
    const dim3 gProj(D_MODEL/128, NROWS/128);   // (8, 32)
    const dim3 gFF1 (D_FF/128,    NROWS/128);   // (32, 32)
    const dim3 gFF2 (D_MODEL/128, NROWS/128);   // (8, 32)
    const dim3 gAttn(SEQ/64, BATCH*N_HEADS);    // (32, 32)

    // h = LN1(x)
    ln_kernel<<<NROWS, blk>>>(x, ln1g, ln1b, h);
    // q/k/v = h @ W^T
    gemm_nt<0><<<gProj, blk>>>(h, wq, nullptr, nullptr, q,  NROWS, D_MODEL, D_MODEL);
    gemm_nt<0><<<gProj, blk>>>(h, wk, nullptr, nullptr, k,  NROWS, D_MODEL, D_MODEL);
    gemm_nt<0><<<gProj, blk>>>(h, wv, nullptr, nullptr, v,  NROWS, D_MODEL, D_MODEL);
    // attention
    flash_kernel<<<gAttn, blk>>>(q, k, v, at);
    // x1 = x + attn @ wo^T
    gemm_nt<1><<<gProj, blk>>>(at, wo, nullptr, x, x1, NROWS, D_MODEL, D_MODEL);
    // h2 = LN2(x1)
    ln_kernel<<<NROWS, blk>>>(x1, ln2g, ln2b, h2);
    // ff = gelu(h2 @ w1^T + b1)
    gemm_nt<2><<<gFF1, blk>>>(h2, w1, b1, nullptr, ff, NROWS, D_FF, D_MODEL);
    // out = x1 + ff @ w2^T + b2
    gemm_nt<3><<<gFF2, blk>>>(ff, w2, b2, x1, out, NROWS, D_MODEL, D_FF);
}

// round 4
// speedup vs baseline: 1.6489x; 1.6489x over previous
#include <cuda_runtime.h>
#include <cuda_bf16.h>
#include <math.h>
#include <cstdint>

#define D_MODEL 1024
#define D_FF    4096
#define N_HEADS 16
#define D_HEAD  64
#define BATCH   2
#define SEQ     2048
#define NROWS   (BATCH*SEQ)   /* 4096 */

#define K3_DM   (3*D_MODEL)   /* 3072  */
#define K3_FF   (3*D_FF)      /* 12288 */

// ---------------- scratch (device globals; no allocation allowed) ----------
__device__ __nv_bfloat16 g_hA  [NROWS * K3_DM];   // LN1(x) triple (hi,hi,lo)
__device__ __nv_bfloat16 g_h2A [NROWS * K3_DM];   // LN2(x1) triple
__device__ __nv_bfloat16 g_atA [NROWS * K3_DM];   // attn out triple
__device__ __nv_bfloat16 g_ffA [NROWS * K3_FF];   // gelu(ffn1) triple
__device__ __nv_bfloat16 g_Bq  [D_MODEL * K3_DM]; // weight triples (hi,lo,hi)
__device__ __nv_bfloat16 g_Bk  [D_MODEL * K3_DM];
__device__ __nv_bfloat16 g_Bv  [D_MODEL * K3_DM];
__device__ __nv_bfloat16 g_Bo  [D_MODEL * K3_DM];
__device__ __nv_bfloat16 g_B1  [D_FF    * K3_DM];
__device__ __nv_bfloat16 g_B2  [D_MODEL * K3_FF];
__device__ float g_q  [NROWS * D_MODEL];
__device__ float g_k  [NROWS * D_MODEL];
__device__ float g_v  [NROWS * D_MODEL];
__device__ float g_at [NROWS * D_MODEL];
__device__ float g_x1 [NROWS * D_MODEL];

// ================= PTX helpers (base-target sm_80-era only) ================
__device__ __forceinline__ uint32_t smem_u32(const void* p) {
    uint32_t a;
    asm("{ .reg .u64 t; cvta.to.shared.u64 t, %1; cvt.u32.u64 %0, t; }" : "=r"(a) : "l"(p));
    return a;
}
__device__ __forceinline__ void cp16(uint32_t s, const void* g) {
    asm volatile("cp.async.cg.shared.global [%0], [%1], 16;" :: "r"(s), "l"(g));
}
#define CP_COMMIT() asm volatile("cp.async.commit_group;" ::: "memory")
#define CP_WAIT(n)  asm volatile("cp.async.wait_group %0;" :: "n"(n) : "memory")

#define LDSM4(r, a) \
    asm volatile("ldmatrix.sync.aligned.m8n8.x4.shared.b16 {%0,%1,%2,%3}, [%4];" \
        : "=r"((r)[0]), "=r"((r)[1]), "=r"((r)[2]), "=r"((r)[3]) : "r"(a))

#define MMA16816(c, a, b0, b1) \
    asm volatile("mma.sync.aligned.m16n8k16.row.col.f32.bf16.bf16.f32 " \
        "{%0,%1,%2,%3}, {%4,%5,%6,%7}, {%8,%9}, {%0,%1,%2,%3};" \
        : "+f"((c)[0]), "+f"((c)[1]), "+f"((c)[2]), "+f"((c)[3]) \
        : "r"((a)[0]), "r"((a)[1]), "r"((a)[2]), "r"((a)[3]), "r"(b0), "r"(b1))

// ---------------- GEMM tiling constants ------------------------------------
#define BM 128
#define BN 128
#define BK 32
#define STAGES 3
#define ROWSTRIDE 40                      /* bf16 elems per smem row (80B) */
#define TILEB (BM * ROWSTRIDE * 2)        /* 10240 bytes per A (or B) tile */
#define STAGEB (2 * TILEB)                /* 20480 per stage */
#define SMEM_GEMM_BYTES (STAGES * STAGEB) /* 61440 */

__device__ __forceinline__ float gelu_exact(float v) {
    return 0.5f * v * (1.0f + erff(v * 0.70710678118654752f));
}

// =========== HMMA GEMM: C[M,N] = A[M,K3] * B[N,K3]^T (bf16 mma.sync) =======
// EPI: 0 plain fp32, 1 +res, 2 gelu(+bias)->bf16 triple (hi,hi,lo), 3 +bias+res
template<int EPI>
__global__ __launch_bounds__(256, 2) void hmma_gemm(
    const __nv_bfloat16* __restrict__ A,   // [M, K3] row-major
    const __nv_bfloat16* __restrict__ B,   // [N, K3] row-major
    const float* __restrict__ bias,
    const float* __restrict__ res,
    float* __restrict__ C,
    __nv_bfloat16* __restrict__ C2,
    int N, int K3)
{
    extern __shared__ char smem[];
    const uint32_t sbase = smem_u32(smem);
    const int tid  = threadIdx.x;
    const int wid  = tid >> 5, lane = tid & 31;
    const int wm   = wid >> 2, wn = wid & 3;       // 2 x 4 warp grid
    const int rowB = blockIdx.y * BM, colB = blockIdx.x * BN;

    // async loader: 512 16B-chunks per tile, 2 per thread per tile
    auto load_stage = [&](int s, int kt) {
        const int k0 = kt * BK;
        const uint32_t sA = sbase + s * STAGEB;
        const uint32_t sB = sA + TILEB;
        const __nv_bfloat16* Ag = A + (size_t)rowB * K3 + k0;
        const __nv_bfloat16* Bg = B + (size_t)colB * K3 + k0;
        #pragma unroll
        for (int i = 0; i < 2; i++) {
            const int c = i * 256 + tid;
            const int r = c >> 2, c16 = c & 3;
            cp16(sA + r * (ROWSTRIDE*2) + c16 * 16, Ag + (size_t)r * K3 + c16 * 8);
            cp16(sB + r * (ROWSTRIDE*2) + c16 * 16, Bg + (size_t)r * K3 + c16 * 8);
        }
        CP_COMMIT();
    };

    float acc[4][4][4];
    #pragma unroll
    for (int i = 0; i < 4; i++)
        #pragma unroll
        for (int j = 0; j < 4; j++)
            #pragma unroll
            for (int q = 0; q < 4; q++) acc[i][j][q] = 0.0f;

    const int ntiles = K3 / BK;
    #pragma unroll
    for (int s = 0; s < STAGES - 1; s++) load_stage(s, s);

    for (int t = 0; t < ntiles; t++) {
        CP_WAIT(STAGES - 2);
        __syncthreads();
        if (t + STAGES - 1 < ntiles) load_stage((t + STAGES - 1) % STAGES, t + STAGES - 1);

        const uint32_t sA = sbase + (t % STAGES) * STAGEB;
        const uint32_t sB = sA + TILEB;
        #pragma unroll
        for (int ks = 0; ks < 2; ks++) {
            uint32_t a[4][4], b[2][4];
            // A fragments: reg order {m0k0, m8k0, m0k8, m8k8}
            #pragma unroll
            for (int mi = 0; mi < 4; mi++) {
                const uint32_t addr = sA
                    + (wm*64 + mi*16 + (lane & 15)) * (ROWSTRIDE*2)
                    + (ks*16 + (lane >> 4) * 8) * 2;
                LDSM4(a[mi], addr);
            }
            // B fragments (non-trans; B smem rows = n, in-row = k):
            // reg0=(n0-7,k0-7) reg1=(n0-7,k8-15) reg2=(n8-15,k0-7) reg3=(n8-15,k8-15)
            #pragma unroll
            for (int nt = 0; nt < 2; nt++) {
                const uint32_t addr = sB
                    + (wn*32 + nt*16 + (lane >> 4) * 8 + (lane & 7)) * (ROWSTRIDE*2)
                    + (ks*16 + ((lane >> 3) & 1) * 8) * 2;
                LDSM4(b[nt], addr);
            }
            #pragma unroll
            for (int mi = 0; mi < 4; mi++) {
                #pragma unroll
                for (int nt = 0; nt < 2; nt++) {
                    MMA16816(acc[mi][nt*2+0], a[mi], b[nt][0], b[nt][1]);
                    MMA16816(acc[mi][nt*2+1], a[mi], b[nt][2], b[nt][3]);
                }
            }
        }
    }

    // ---------------- epilogue (register -> gmem) ----------------
    const int g  = lane >> 2;
    const int tq = lane & 3;
    #pragma unroll
    for (int mi = 0; mi < 4; mi++) {
        #pragma unroll
        for (int half = 0; half < 2; half++) {
            const int gr = rowB + wm*64 + mi*16 + g + half*8;
            #pragma unroll
            for (int ni = 0; ni < 4; ni++) {
                const int gc = colB + wn*32 + ni*8 + tq*2;
                float v0 = acc[mi][ni][half*2+0];
                float v1 = acc[mi][ni][half*2+1];
                if (EPI == 0) {
                    *reinterpret_cast<float2*>(C + (size_t)gr * N + gc) = make_float2(v0, v1);
                } else if (EPI == 1) {
                    const float2 r2 = *reinterpret_cast<const float2*>(res + (size_t)gr * N + gc);
                    *reinterpret_cast<float2*>(C + (size_t)gr * N + gc) =
                        make_float2(v0 + r2.x, v1 + r2.y);
                } else if (EPI == 2) {
                    const float g0 = gelu_exact(v0 + bias[gc]);
                    const float g1 = gelu_exact(v1 + bias[gc + 1]);
                    __nv_bfloat162 hi2, lo2;
                    hi2.x = __float2bfloat16(g0);
                    hi2.y = __float2bfloat16(g1);
                    lo2.x = __float2bfloat16(g0 - __bfloat162float(hi2.x));
                    lo2.y = __float2bfloat16(g1 - __bfloat162float(hi2.y));
                    const size_t base = (size_t)gr * (3 * (size_t)N) + gc;
                    *reinterpret_cast<__nv_bfloat162*>(C2 + base)         = hi2;
                    *reinterpret_cast<__nv_bfloat162*>(C2 + base + N)     = hi2;
                    *reinterpret_cast<__nv_bfloat162*>(C2 + base + 2*N)   = lo2;
                } else {
                    const float2 r2 = *reinterpret_cast<const float2*>(res + (size_t)gr * N + gc);
                    *reinterpret_cast<float2*>(C + (size_t)gr * N + gc) =
                        make_float2(v0 + bias[gc] + r2.x, v1 + bias[gc + 1] + r2.y);
                }
            }
        }
    }
}

// ---------------- layernorm -> bf16 triple (hi,hi,lo) ----------------------
__global__ __launch_bounds__(256) void ln_triple(const float* __restrict__ x,
        const float* __restrict__ g, const float* __restrict__ b,
        __nv_bfloat16* __restrict__ out)
{
    __shared__ float red[256];
    const int row = blockIdx.x, t = threadIdx.x;
    const float4 v = reinterpret_cast<const float4*>(x + (size_t)row * D_MODEL)[t];
    red[t] = v.x + v.y + v.z + v.w;
    __syncthreads();
    #pragma unroll
    for (int o = 128; o > 0; o >>= 1) { if (t < o) red[t] += red[t + o]; __syncthreads(); }
    const float mu = red[0] * (1.0f / D_MODEL);
    __syncthreads();
    const float dx = v.x - mu, dy = v.y - mu, dz = v.z - mu, dw = v.w - mu;
    red[t] = dx*dx + dy*dy + dz*dz + dw*dw;
    __syncthreads();
    #pragma unroll
    for (int o = 128; o > 0; o >>= 1) { if (t < o) red[t] += red[t + o]; __syncthreads(); }
    const float rs = rsqrtf(red[0] * (1.0f / D_MODEL) + 1e-5f);
    const float4 gv = reinterpret_cast<const float4*>(g)[t];
    const float4 bv = reinterpret_cast<const float4*>(b)[t];
    float o4[4] = { dx*rs*gv.x + bv.x, dy*rs*gv.y + bv.y, dz*rs*gv.z + bv.z, dw*rs*gv.w + bv.w };
    __nv_bfloat16 h[4], l[4];
    #pragma unroll
    for (int j = 0; j < 4; j++) {
        h[j] = __float2bfloat16(o4[j]);
        l[j] = __float2bfloat16(o4[j] - __bfloat162float(h[j]));
    }
    const size_t base = (size_t)row * K3_DM + t * 4;
    *reinterpret_cast<uint2*>(out + base)               = *reinterpret_cast<uint2*>(h);
    *reinterpret_cast<uint2*>(out + base + D_MODEL)     = *reinterpret_cast<uint2*>(h);
    *reinterpret_cast<uint2*>(out + base + 2 * D_MODEL) = *reinterpret_cast<uint2*>(l);
}

// ---------------- fp32 -> bf16 triple converter ----------------------------
// MODE 0 (A-side): hi,hi,lo   MODE 1 (B-side): hi,lo,hi
template<int MODE>
__global__ __launch_bounds__(256) void conv_triple(const float* __restrict__ src,
        __nv_bfloat16* __restrict__ dst, int K, int total)
{
    const int i4 = blockIdx.x * 256 + threadIdx.x;
    if (i4 * 4 >= total) return;
    const float4 v = reinterpret_cast<const float4*>(src)[i4];
    const int idx = i4 * 4;
    const int row = idx / K, col = idx - row * K;
    float o4[4] = { v.x, v.y, v.z, v.w };
    __nv_bfloat16 h[4], l[4];
    #pragma unroll
    for (int j = 0; j < 4; j++) {
        h[j] = __float2bfloat16(o4[j]);
        l[j] = __float2bfloat16(o4[j] - __bfloat162float(h[j]));
    }
    const size_t base = (size_t)row * 3 * K + col;
    *reinterpret_cast<uint2*>(dst + base) = *reinterpret_cast<uint2*>(h);
    if (MODE == 0) {
        *reinterpret_cast<uint2*>(dst + base + K)     = *reinterpret_cast<uint2*>(h);
        *reinterpret_cast<uint2*>(dst + base + 2 * K) = *reinterpret_cast<uint2*>(l);
    } else {
        *reinterpret_cast<uint2*>(dst + base + K)     = *reinterpret_cast<uint2*>(l);
        *reinterpret_cast<uint2*>(dst + base + 2 * K) = *reinterpret_cast<uint2*>(h);
    }
}

// ---------------- flash attention: BQ=64, BK=32, d_head=64 (fp32) ----------
__global__ __launch_bounds__(256) void flash_kernel(const float* __restrict__ Q,
        const float* __restrict__ Km, const float* __restrict__ V,
        float* __restrict__ O)
{
    __shared__ float QsT[64][68];
    __shared__ float KsT[64][34];
    __shared__ float Vs [32][68];
    __shared__ float PsT[32][68];
    const int t  = threadIdx.x;
    const int tx = t & 15, ty = t >> 4;
    const int bh = blockIdx.y;
    const size_t base = (size_t)(bh >> 4) * SEQ * D_MODEL + (size_t)(bh & 15) * D_HEAD;
    const int qb = blockIdx.x * 64;

    #pragma unroll
    for (int i = 0; i < 4; i++) {
        const int lin = i * 256 + t;
        const int row = lin >> 4, d = (lin & 15) * 4;
        float4 v = *reinterpret_cast<const float4*>(Q + base + (size_t)(qb + row) * D_MODEL + d);
        QsT[d+0][row] = v.x * 0.125f; QsT[d+1][row] = v.y * 0.125f;
        QsT[d+2][row] = v.z * 0.125f; QsT[d+3][row] = v.w * 0.125f;
    }

    float m[4], l[4], o[4][4];
    #pragma unroll
    for (int i = 0; i < 4; i++) {
        m[i] = -1e30f; l[i] = 0.0f;
        #pragma unroll
        for (int j = 0; j < 4; j++) o[i][j] = 0.0f;
    }

    for (int kt = 0; kt < SEQ; kt += 32) {
        __syncthreads();
        #pragma unroll
        for (int i = 0; i < 2; i++) {
            const int lin = i * 256 + t;
            const int row = lin >> 4, d = (lin & 15) * 4;
            const size_t goff = base + (size_t)(kt + row) * D_MODEL + d;
            float4 kv = *reinterpret_cast<const float4*>(Km + goff);
            KsT[d+0][row] = kv.x; KsT[d+1][row] = kv.y;
            KsT[d+2][row] = kv.z; KsT[d+3][row] = kv.w;
            float4 vv = *reinterpret_cast<const float4*>(V + goff);
            *reinterpret_cast<float4*>(&Vs[row][d]) = vv;
        }
        __syncthreads();

        float s[4][2] = {};
        #pragma unroll 8
        for (int kd = 0; kd < 64; kd++) {
            float4 qv = *reinterpret_cast<const float4*>(&QsT[kd][ty*4]);
            float2 kv = *reinterpret_cast<const float2*>(&KsT[kd][tx*2]);
            s[0][0] = fmaf(qv.x, kv.x, s[0][0]); s[0][1] = fmaf(qv.x, kv.y, s[0][1]);
            s[1][0] = fmaf(qv.y, kv.x, s[1][0]); s[1][1] = fmaf(qv.y, kv.y, s[1][1]);
            s[2][0] = fmaf(qv.z, kv.x, s[2][0]); s[2][1] = fmaf(qv.z, kv.y, s[2][1]);
            s[3][0] = fmaf(qv.w, kv.x, s[3][0]); s[3][1] = fmaf(qv.w, kv.y, s[3][1]);
        }

        #pragma unroll
        for (int i = 0; i < 4; i++) {
            float mx = fmaxf(s[i][0], s[i][1]);
            #pragma unroll
            for (int off = 8; off > 0; off >>= 1)
                mx = fmaxf(mx, __shfl_xor_sync(0xffffffffu, mx, off));
            const float mn   = fmaxf(m[i], mx);
            const float corr = __expf(m[i] - mn);
            const float p0 = __expf(s[i][0] - mn);
            const float p1 = __expf(s[i][1] - mn);
            float sm = p0 + p1;
            #pragma unroll
            for (int off = 8; off > 0; off >>= 1)
                sm += __shfl_xor_sync(0xffffffffu, sm, off);
            l[i] = l[i] * corr + sm;
            m[i] = mn;
            o[i][0] *= corr; o[i][1] *= corr; o[i][2] *= corr; o[i][3] *= corr;
            PsT[tx*2 + 0][ty*4 + i] = p0;
            PsT[tx*2 + 1][ty*4 + i] = p1;
        }
        __syncthreads();

        #pragma unroll 4
        for (int j = 0; j < 32; j++) {
            float4 p4 = *reinterpret_cast<const float4*>(&PsT[j][ty*4]);
            float4 v4 = *reinterpret_cast<const float4*>(&Vs[j][tx*4]);
            float pj[4] = {p4.x, p4.y, p4.z, p4.w};
            float vj[4] = {v4.x, v4.y, v4.z, v4.w};
            #pragma unroll
            for (int i = 0; i < 4; i++)
                #pragma unroll
                for (int d = 0; d < 4; d++)
                    o[i][d] = fmaf(pj[i], vj[d], o[i][d]);
        }
    }

    #pragma unroll
    for (int i = 0; i < 4; i++) {
        const float inv = 1.0f / l[i];
        float4 o4 = make_float4(o[i][0]*inv, o[i][1]*inv, o[i][2]*inv, o[i][3]*inv);
        *reinterpret_cast<float4*>(O + base + (size_t)(qb + ty*4 + i) * D_MODEL + tx*4) = o4;
    }
}

// ---------------- launch --------------------------------------------------
extern "C" void kernel_launch(void* const* d_in, const int* in_sizes, int n_in,
                              void* d_out, int out_size)
{
    const float* x    = (const float*)d_in[0];
    const float* wq   = (const float*)d_in[1];
    const float* wk   = (const float*)d_in[2];
    const float* wv   = (const float*)d_in[3];
    const float* wo   = (const float*)d_in[4];
    const float* w1   = (const float*)d_in[5];
    const float* b1   = (const float*)d_in[6];
    const float* w2   = (const float*)d_in[7];
    const float* b2   = (const float*)d_in[8];
    const float* ln1g = (const float*)d_in[9];
    const float* ln1b = (const float*)d_in[10];
    const float* ln2g = (const float*)d_in[11];
    const float* ln2b = (const float*)d_in[12];
    float* out = (float*)d_out;

    __nv_bfloat16 *hA, *h2A, *atA, *ffA, *Bq, *Bk, *Bv, *Bo, *B1, *B2;
    float *q, *k, *v, *at, *x1;
    cudaGetSymbolAddress((void**)&hA,  g_hA);
    cudaGetSymbolAddress((void**)&h2A, g_h2A);
    cudaGetSymbolAddress((void**)&atA, g_atA);
    cudaGetSymbolAddress((void**)&ffA, g_ffA);
    cudaGetSymbolAddress((void**)&Bq,  g_Bq);
    cudaGetSymbolAddress((void**)&Bk,  g_Bk);
    cudaGetSymbolAddress((void**)&Bv,  g_Bv);
    cudaGetSymbolAddress((void**)&Bo,  g_Bo);
    cudaGetSymbolAddress((void**)&B1,  g_B1);
    cudaGetSymbolAddress((void**)&B2,  g_B2);
    cudaGetSymbolAddress((void**)&q,   g_q);
    cudaGetSymbolAddress((void**)&k,   g_k);
    cudaGetSymbolAddress((void**)&v,   g_v);
    cudaGetSymbolAddress((void**)&at,  g_at);
    cudaGetSymbolAddress((void**)&x1,  g_x1);

    cudaFuncSetAttribute(hmma_gemm<0>, cudaFuncAttributeMaxDynamicSharedMemorySize, SMEM_GEMM_BYTES);
    cudaFuncSetAttribute(hmma_gemm<1>, cudaFuncAttributeMaxDynamicSharedMemorySize, SMEM_GEMM_BYTES);
    cudaFuncSetAttribute(hmma_gemm<2>, cudaFuncAttributeMaxDynamicSharedMemorySize, SMEM_GEMM_BYTES);
    cudaFuncSetAttribute(hmma_gemm<3>, cudaFuncAttributeMaxDynamicSharedMemorySize, SMEM_GEMM_BYTES);

    const dim3 blk(256);
    const dim3 gP (D_MODEL/BN, NROWS/BM);    // (8, 32)
    const dim3 gF1(D_FF/BN,    NROWS/BM);    // (32, 32)
    const dim3 gAttn(SEQ/64, BATCH*N_HEADS); // (32, 32)

    // weight conversions
    conv_triple<1><<<(D_MODEL*D_MODEL/4+255)/256, blk>>>(wq, Bq, D_MODEL, D_MODEL*D_MODEL);
    conv_triple<1><<<(D_MODEL*D_MODEL/4+255)/256, blk>>>(wk, Bk, D_MODEL, D_MODEL*D_MODEL);
    conv_triple<1><<<(D_MODEL*D_MODEL/4+255)/256, blk>>>(wv, Bv, D_MODEL, D_MODEL*D_MODEL);
    conv_triple<1><<<(D_MODEL*D_MODEL/4+255)/256, blk>>>(wo, Bo, D_MODEL, D_MODEL*D_MODEL);
    conv_triple<1><<<(D_FF*D_MODEL/4+255)/256,    blk>>>(w1, B1, D_MODEL, D_FF*D_MODEL);
    conv_triple<1><<<(D_MODEL*D_FF/4+255)/256,    blk>>>(w2, B2, D_FF,    D_MODEL*D_FF);

    // h = LN1(x) -> triple
    ln_triple<<<NROWS, blk>>>(x, ln1g, ln1b, hA);
    // q/k/v projections
    hmma_gemm<0><<<gP, blk, SMEM_GEMM_BYTES>>>(hA, Bq, nullptr, nullptr, q,  nullptr, D_MODEL, K3_DM);
    hmma_gemm<0><<<gP, blk, SMEM_GEMM_BYTES>>>(hA, Bk, nullptr, nullptr, k,  nullptr, D_MODEL, K3_DM);
    hmma_gemm<0><<<gP, blk, SMEM_GEMM_BYTES>>>(hA, Bv, nullptr, nullptr, v,  nullptr, D_MODEL, K3_DM);
    // attention
    flash_kernel<<<gAttn, blk>>>(q, k, v, at);
    // at -> triple
    conv_triple<0><<<(NROWS*D_MODEL/4+255)/256, blk>>>(at, atA, D_MODEL, NROWS*D_MODEL);
    // x1 = x + at @ wo^T
    hmma_gemm<1><<<gP, blk, SMEM_GEMM_BYTES>>>(atA, Bo, nullptr, x, x1, nullptr, D_MODEL, K3_DM);
    // h2 = LN2(x1) -> triple
    ln_triple<<<NROWS, blk>>>(x1, ln2g, ln2b, h2A);
    // ff = gelu(h2 @ w1^T + b1) -> triple
    hmma_gemm<2><<<gF1, blk, SMEM_GEMM_BYTES>>>(h2A, B1, b1, nullptr, nullptr, ffA, D_FF, K3_DM);
    // out = x1 + ff @ w2^T + b2
    hmma_gemm<3><<<gP, blk, SMEM_GEMM_BYTES>>>(ffA, B2, b2, x1, out, nullptr, D_MODEL, K3_FF);
}

// round 5
// speedup vs baseline: 2.5169x; 1.5264x over previous
#include <cuda_runtime.h>
#include <cuda_bf16.h>
#include <math.h>
#include <cstdint>

#define D_MODEL 1024
#define D_FF    4096
#define N_HEADS 16
#define D_HEAD  64
#define BATCH   2
#define SEQ     2048
#define NROWS   (BATCH*SEQ)   /* 4096 */

#define K3_DM   (3*D_MODEL)   /* 3072  */
#define K3_FF   (3*D_FF)      /* 12288 */

// ---------------- scratch (device globals; no allocation allowed) ----------
__device__ __nv_bfloat16 g_hA  [NROWS * K3_DM];   // LN1(x) triple (hi,hi,lo)
__device__ __nv_bfloat16 g_h2A [NROWS * K3_DM];   // LN2(x1) triple
__device__ __nv_bfloat16 g_atA [NROWS * K3_DM];   // attn out triple (written by flash)
__device__ __nv_bfloat16 g_ffA [NROWS * K3_FF];   // gelu(ffn1) triple
__device__ __nv_bfloat16 g_Bq  [D_MODEL * K3_DM]; // weight triples (hi,lo,hi)
__device__ __nv_bfloat16 g_Bk  [D_MODEL * K3_DM];
__device__ __nv_bfloat16 g_Bv  [D_MODEL * K3_DM];
__device__ __nv_bfloat16 g_Bo  [D_MODEL * K3_DM];
__device__ __nv_bfloat16 g_B1  [D_FF    * K3_DM];
__device__ __nv_bfloat16 g_B2  [D_MODEL * K3_FF];
// split bf16 planes for q/k/v (q pre-scaled by 0.125)
__device__ __nv_bfloat16 g_qh [NROWS * D_MODEL];
__device__ __nv_bfloat16 g_ql [NROWS * D_MODEL];
__device__ __nv_bfloat16 g_kh [NROWS * D_MODEL];
__device__ __nv_bfloat16 g_kl [NROWS * D_MODEL];
__device__ __nv_bfloat16 g_vh [NROWS * D_MODEL];
__device__ __nv_bfloat16 g_vl [NROWS * D_MODEL];
__device__ float g_x1 [NROWS * D_MODEL];

// ================= PTX helpers (base-target sm_80-era only) ================
__device__ __forceinline__ uint32_t smem_u32(const void* p) {
    uint32_t a;
    asm("{ .reg .u64 t; cvta.to.shared.u64 t, %1; cvt.u32.u64 %0, t; }" : "=r"(a) : "l"(p));
    return a;
}
__device__ __forceinline__ void cp16(uint32_t s, const void* g) {
    asm volatile("cp.async.cg.shared.global [%0], [%1], 16;" :: "r"(s), "l"(g));
}
#define CP_COMMIT() asm volatile("cp.async.commit_group;" ::: "memory")
#define CP_WAIT(n)  asm volatile("cp.async.wait_group %0;" :: "n"(n) : "memory")

#define LDSM4(r, a) \
    asm volatile("ldmatrix.sync.aligned.m8n8.x4.shared.b16 {%0,%1,%2,%3}, [%4];" \
        : "=r"((r)[0]), "=r"((r)[1]), "=r"((r)[2]), "=r"((r)[3]) : "r"(a))
#define LDSM4T(r, a) \
    asm volatile("ldmatrix.sync.aligned.m8n8.x4.trans.shared.b16 {%0,%1,%2,%3}, [%4];" \
        : "=r"((r)[0]), "=r"((r)[1]), "=r"((r)[2]), "=r"((r)[3]) : "r"(a))

#define MMA16816(c, a, b0, b1) \
    asm volatile("mma.sync.aligned.m16n8k16.row.col.f32.bf16.bf16.f32 " \
        "{%0,%1,%2,%3}, {%4,%5,%6,%7}, {%8,%9}, {%0,%1,%2,%3};" \
        : "+f"((c)[0]), "+f"((c)[1]), "+f"((c)[2]), "+f"((c)[3]) \
        : "r"((a)[0]), "r"((a)[1]), "r"((a)[2]), "r"((a)[3]), "r"(b0), "r"(b1))

// ---------------- GEMM tiling constants ------------------------------------
#define BM 128
#define BN 128
#define BK 32
#define STAGES 3
#define ROWSTRIDE 40                      /* bf16 elems per smem row (80B) */
#define TILEB (BM * ROWSTRIDE * 2)        /* 10240 bytes per A (or B) tile */
#define STAGEB (2 * TILEB)                /* 20480 per stage */
#define SMEM_GEMM_BYTES (STAGES * STAGEB) /* 61440 */

__device__ __forceinline__ float gelu_exact(float v) {
    return 0.5f * v * (1.0f + erff(v * 0.70710678118654752f));
}

// =========== HMMA GEMM: C[M,N] = A[M,K3] * B[N,K3]^T (bf16 mma.sync) =======
// EPI: 0 plain fp32, 1 +res, 2 gelu(+bias)->bf16 triple (hi,hi,lo),
//      3 +bias+res, 4 split bf16 planes (Ch,Cl) with scale
template<int EPI>
__global__ __launch_bounds__(256, 2) void hmma_gemm(
    const __nv_bfloat16* __restrict__ A,   // [M, K3] row-major
    const __nv_bfloat16* __restrict__ B,   // [N, K3] row-major
    const float* __restrict__ bias,
    const float* __restrict__ res,
    float* __restrict__ C,
    __nv_bfloat16* __restrict__ C2,        // triple (EPI2) or hi plane (EPI4)
    __nv_bfloat16* __restrict__ Cl,        // lo plane (EPI4)
    float scale,
    int N, int K3)
{
    extern __shared__ char smem[];
    const uint32_t sbase = smem_u32(smem);
    const int tid  = threadIdx.x;
    const int wid  = tid >> 5, lane = tid & 31;
    const int wm   = wid >> 2, wn = wid & 3;       // 2 x 4 warp grid
    const int rowB = blockIdx.y * BM, colB = blockIdx.x * BN;

    auto load_stage = [&](int s, int kt) {
        const int k0 = kt * BK;
        const uint32_t sA = sbase + s * STAGEB;
        const uint32_t sB = sA + TILEB;
        const __nv_bfloat16* Ag = A + (size_t)rowB * K3 + k0;
        const __nv_bfloat16* Bg = B + (size_t)colB * K3 + k0;
        #pragma unroll
        for (int i = 0; i < 2; i++) {
            const int c = i * 256 + tid;
            const int r = c >> 2, c16 = c & 3;
            cp16(sA + r * (ROWSTRIDE*2) + c16 * 16, Ag + (size_t)r * K3 + c16 * 8);
            cp16(sB + r * (ROWSTRIDE*2) + c16 * 16, Bg + (size_t)r * K3 + c16 * 8);
        }
        CP_COMMIT();
    };

    float acc[4][4][4];
    #pragma unroll
    for (int i = 0; i < 4; i++)
        #pragma unroll
        for (int j = 0; j < 4; j++)
            #pragma unroll
            for (int q = 0; q < 4; q++) acc[i][j][q] = 0.0f;

    const int ntiles = K3 / BK;
    #pragma unroll
    for (int s = 0; s < STAGES - 1; s++) load_stage(s, s);

    for (int t = 0; t < ntiles; t++) {
        CP_WAIT(STAGES - 2);
        __syncthreads();
        if (t + STAGES - 1 < ntiles) load_stage((t + STAGES - 1) % STAGES, t + STAGES - 1);

        const uint32_t sA = sbase + (t % STAGES) * STAGEB;
        const uint32_t sB = sA + TILEB;
        #pragma unroll
        for (int ks = 0; ks < 2; ks++) {
            uint32_t a[4][4], b[2][4];
            #pragma unroll
            for (int mi = 0; mi < 4; mi++) {
                const uint32_t addr = sA
                    + (wm*64 + mi*16 + (lane & 15)) * (ROWSTRIDE*2)
                    + (ks*16 + (lane >> 4) * 8) * 2;
                LDSM4(a[mi], addr);
            }
            #pragma unroll
            for (int nt = 0; nt < 2; nt++) {
                const uint32_t addr = sB
                    + (wn*32 + nt*16 + (lane >> 4) * 8 + (lane & 7)) * (ROWSTRIDE*2)
                    + (ks*16 + ((lane >> 3) & 1) * 8) * 2;
                LDSM4(b[nt], addr);
            }
            #pragma unroll
            for (int mi = 0; mi < 4; mi++) {
                #pragma unroll
                for (int nt = 0; nt < 2; nt++) {
                    MMA16816(acc[mi][nt*2+0], a[mi], b[nt][0], b[nt][1]);
                    MMA16816(acc[mi][nt*2+1], a[mi], b[nt][2], b[nt][3]);
                }
            }
        }
    }

    const int g  = lane >> 2;
    const int tq = lane & 3;
    #pragma unroll
    for (int mi = 0; mi < 4; mi++) {
        #pragma unroll
        for (int half = 0; half < 2; half++) {
            const int gr = rowB + wm*64 + mi*16 + g + half*8;
            #pragma unroll
            for (int ni = 0; ni < 4; ni++) {
                const int gc = colB + wn*32 + ni*8 + tq*2;
                float v0 = acc[mi][ni][half*2+0];
                float v1 = acc[mi][ni][half*2+1];
                if (EPI == 0) {
                    *reinterpret_cast<float2*>(C + (size_t)gr * N + gc) = make_float2(v0, v1);
                } else if (EPI == 1) {
                    const float2 r2 = *reinterpret_cast<const float2*>(res + (size_t)gr * N + gc);
                    *reinterpret_cast<float2*>(C + (size_t)gr * N + gc) =
                        make_float2(v0 + r2.x, v1 + r2.y);
                } else if (EPI == 2) {
                    const float g0 = gelu_exact(v0 + bias[gc]);
                    const float g1 = gelu_exact(v1 + bias[gc + 1]);
                    __nv_bfloat162 hi2, lo2;
                    hi2.x = __float2bfloat16(g0);
                    hi2.y = __float2bfloat16(g1);
                    lo2.x = __float2bfloat16(g0 - __bfloat162float(hi2.x));
                    lo2.y = __float2bfloat16(g1 - __bfloat162float(hi2.y));
                    const size_t base = (size_t)gr * (3 * (size_t)N) + gc;
                    *reinterpret_cast<__nv_bfloat162*>(C2 + base)         = hi2;
                    *reinterpret_cast<__nv_bfloat162*>(C2 + base + N)     = hi2;
                    *reinterpret_cast<__nv_bfloat162*>(C2 + base + 2*N)   = lo2;
                } else if (EPI == 3) {
                    const float2 r2 = *reinterpret_cast<const float2*>(res + (size_t)gr * N + gc);
                    *reinterpret_cast<float2*>(C + (size_t)gr * N + gc) =
                        make_float2(v0 + bias[gc] + r2.x, v1 + bias[gc + 1] + r2.y);
                } else {  // EPI == 4: split planes with scale
                    const float s0 = v0 * scale, s1 = v1 * scale;
                    __nv_bfloat162 hi2, lo2;
                    hi2.x = __float2bfloat16(s0);
                    hi2.y = __float2bfloat16(s1);
                    lo2.x = __float2bfloat16(s0 - __bfloat162float(hi2.x));
                    lo2.y = __float2bfloat16(s1 - __bfloat162float(hi2.y));
                    *reinterpret_cast<__nv_bfloat162*>(C2 + (size_t)gr * N + gc) = hi2;
                    *reinterpret_cast<__nv_bfloat162*>(Cl + (size_t)gr * N + gc) = lo2;
                }
            }
        }
    }
}

// ---------------- layernorm -> bf16 triple (hi,hi,lo) ----------------------
__global__ __launch_bounds__(256) void ln_triple(const float* __restrict__ x,
        const float* __restrict__ g, const float* __restrict__ b,
        __nv_bfloat16* __restrict__ out)
{
    __shared__ float red[256];
    const int row = blockIdx.x, t = threadIdx.x;
    const float4 v = reinterpret_cast<const float4*>(x + (size_t)row * D_MODEL)[t];
    red[t] = v.x + v.y + v.z + v.w;
    __syncthreads();
    #pragma unroll
    for (int o = 128; o > 0; o >>= 1) { if (t < o) red[t] += red[t + o]; __syncthreads(); }
    const float mu = red[0] * (1.0f / D_MODEL);
    __syncthreads();
    const float dx = v.x - mu, dy = v.y - mu, dz = v.z - mu, dw = v.w - mu;
    red[t] = dx*dx + dy*dy + dz*dz + dw*dw;
    __syncthreads();
    #pragma unroll
    for (int o = 128; o > 0; o >>= 1) { if (t < o) red[t] += red[t + o]; __syncthreads(); }
    const float rs = rsqrtf(red[0] * (1.0f / D_MODEL) + 1e-5f);
    const float4 gv = reinterpret_cast<const float4*>(g)[t];
    const float4 bv = reinterpret_cast<const float4*>(b)[t];
    float o4[4] = { dx*rs*gv.x + bv.x, dy*rs*gv.y + bv.y, dz*rs*gv.z + bv.z, dw*rs*gv.w + bv.w };
    __nv_bfloat16 h[4], l[4];
    #pragma unroll
    for (int j = 0; j < 4; j++) {
        h[j] = __float2bfloat16(o4[j]);
        l[j] = __float2bfloat16(o4[j] - __bfloat162float(h[j]));
    }
    const size_t base = (size_t)row * K3_DM + t * 4;
    *reinterpret_cast<uint2*>(out + base)               = *reinterpret_cast<uint2*>(h);
    *reinterpret_cast<uint2*>(out + base + D_MODEL)     = *reinterpret_cast<uint2*>(h);
    *reinterpret_cast<uint2*>(out + base + 2 * D_MODEL) = *reinterpret_cast<uint2*>(l);
}

// ---------------- fp32 -> bf16 triple converter (B-side: hi,lo,hi) ---------
__global__ __launch_bounds__(256) void conv_triple_b(const float* __restrict__ src,
        __nv_bfloat16* __restrict__ dst, int K, int total)
{
    const int i4 = blockIdx.x * 256 + threadIdx.x;
    if (i4 * 4 >= total) return;
    const float4 v = reinterpret_cast<const float4*>(src)[i4];
    const int idx = i4 * 4;
    const int row = idx / K, col = idx - row * K;
    float o4[4] = { v.x, v.y, v.z, v.w };
    __nv_bfloat16 h[4], l[4];
    #pragma unroll
    for (int j = 0; j < 4; j++) {
        h[j] = __float2bfloat16(o4[j]);
        l[j] = __float2bfloat16(o4[j] - __bfloat162float(h[j]));
    }
    const size_t base = (size_t)row * 3 * K + col;
    *reinterpret_cast<uint2*>(dst + base)         = *reinterpret_cast<uint2*>(h);
    *reinterpret_cast<uint2*>(dst + base + K)     = *reinterpret_cast<uint2*>(l);
    *reinterpret_cast<uint2*>(dst + base + 2 * K) = *reinterpret_cast<uint2*>(h);
}

// ========== flash attention on tensor cores (BQ=64, TK=64, 4 warps) ========
// smem layout (bytes), row stride 144 B (72 bf16):
//   QH 0, QL 9216, then per buf b: 18432 + b*36864 + {KH 0, KL 9216, VH 18432, VL 27648}
#define FSTRIDE 144
#define FTILEB  (64 * FSTRIDE)         /* 9216 */
#define FQ_BYTES (2 * FTILEB)          /* 18432 */
#define FKV_BYTES (4 * FTILEB)         /* 36864 */
#define SMEM_FLASH_BYTES (FQ_BYTES + 2 * FKV_BYTES)  /* 92160 */

__global__ __launch_bounds__(128, 2) void flash_mma(
        const __nv_bfloat16* __restrict__ Qh, const __nv_bfloat16* __restrict__ Ql,
        const __nv_bfloat16* __restrict__ Kh, const __nv_bfloat16* __restrict__ Kl,
        const __nv_bfloat16* __restrict__ Vh, const __nv_bfloat16* __restrict__ Vl,
        __nv_bfloat16* __restrict__ outA)
{
    extern __shared__ char smem[];
    const uint32_t sb = smem_u32(smem);
    const int tid = threadIdx.x;
    const int w = tid >> 5, lane = tid & 31;
    const int bh = blockIdx.y;                       // 0..31
    const size_t base = (size_t)(bh >> 4) * SEQ * D_MODEL + (size_t)(bh & 15) * D_HEAD;
    const int qb = blockIdx.x * 64;

    // ---- load Q tile (both planes) via cp.async: 64 rows x 8 chunks per plane
    {
        #pragma unroll
        for (int i = 0; i < 4; i++) {
            const int c = i * 128 + tid;
            const int row = c >> 3, seg = c & 7;
            const size_t goff = base + (size_t)(qb + row) * D_MODEL + seg * 8;
            cp16(sb + 0      + row * FSTRIDE + seg * 16, Qh + goff);
            cp16(sb + FTILEB + row * FSTRIDE + seg * 16, Ql + goff);
        }
    }
    auto load_kv = [&](int buf, int kt) {
        const uint32_t kvb = sb + FQ_BYTES + buf * FKV_BYTES;
        #pragma unroll
        for (int i = 0; i < 4; i++) {
            const int c = i * 128 + tid;
            const int row = c >> 3, seg = c & 7;
            const size_t goff = base + (size_t)(kt + row) * D_MODEL + seg * 8;
            const uint32_t soff = row * FSTRIDE + seg * 16;
            cp16(kvb + 0*FTILEB + soff, Kh + goff);
            cp16(kvb + 1*FTILEB + soff, Kl + goff);
            cp16(kvb + 2*FTILEB + soff, Vh + goff);
            cp16(kvb + 3*FTILEB + soff, Vl + goff);
        }
        CP_COMMIT();
    };
    load_kv(0, 0);

    float m0 = -1e30f, m1 = -1e30f, l0 = 0.0f, l1 = 0.0f;
    float o[8][4];
    #pragma unroll
    for (int j = 0; j < 8; j++)
        #pragma unroll
        for (int q = 0; q < 4; q++) o[j][q] = 0.0f;

    const uint32_t aQrow = (w*16 + (lane & 15)) * FSTRIDE + (lane >> 4) * 16;
    const uint32_t bKrow = ((lane >> 4) * 8 + (lane & 7)) * FSTRIDE + ((lane >> 3) & 1) * 16;
    const uint32_t bVrow = (lane & 15) * FSTRIDE + (lane >> 4) * 16;

    for (int ti = 0; ti < SEQ / 64; ti++) {
        CP_WAIT(0);
        __syncthreads();
        if (ti + 1 < SEQ / 64) load_kv((ti + 1) & 1, (ti + 1) * 64);
        const uint32_t kvb = sb + FQ_BYTES + (ti & 1) * FKV_BYTES;

        // ---- S = qh*kh + qh*kl + ql*kh  (M=16/warp, N=64 keys, K=64 d per pass)
        float s[8][4];
        #pragma unroll
        for (int j = 0; j < 8; j++)
            #pragma unroll
            for (int q = 0; q < 4; q++) s[j][q] = 0.0f;
        #pragma unroll
        for (int pass = 0; pass < 3; pass++) {
            const uint32_t Apl = sb + (pass == 2 ? FTILEB : 0);
            const uint32_t Bpl = kvb + (pass == 1 ? FTILEB : 0);
            #pragma unroll
            for (int ks = 0; ks < 4; ks++) {
                uint32_t a[4];
                LDSM4(a, Apl + aQrow + ks * 32);
                #pragma unroll
                for (int nt = 0; nt < 4; nt++) {
                    uint32_t b[4];
                    LDSM4(b, Bpl + bKrow + (nt*16) * FSTRIDE + ks * 32);
                    MMA16816(s[nt*2+0], a, b[0], b[1]);
                    MMA16816(s[nt*2+1], a, b[2], b[3]);
                }
            }
        }

        // ---- online softmax (rows g = lane>>2 and g+8 within warp's 16 rows)
        float mx0 = -1e30f, mx1 = -1e30f;
        #pragma unroll
        for (int j = 0; j < 8; j++) {
            mx0 = fmaxf(mx0, fmaxf(s[j][0], s[j][1]));
            mx1 = fmaxf(mx1, fmaxf(s[j][2], s[j][3]));
        }
        mx0 = fmaxf(mx0, __shfl_xor_sync(0xffffffffu, mx0, 1));
        mx0 = fmaxf(mx0, __shfl_xor_sync(0xffffffffu, mx0, 2));
        mx1 = fmaxf(mx1, __shfl_xor_sync(0xffffffffu, mx1, 1));
        mx1 = fmaxf(mx1, __shfl_xor_sync(0xffffffffu, mx1, 2));
        const float mn0 = fmaxf(m0, mx0), mn1 = fmaxf(m1, mx1);
        const float corr0 = __expf(m0 - mn0), corr1 = __expf(m1 - mn1);
        m0 = mn0; m1 = mn1;

        float sum0 = 0.0f, sum1 = 0.0f;
        uint32_t aph[16], apl[16];
        #pragma unroll
        for (int j = 0; j < 8; j++) {
            float p0 = __expf(s[j][0] - mn0), p1 = __expf(s[j][1] - mn0);
            float p2 = __expf(s[j][2] - mn1), p3 = __expf(s[j][3] - mn1);
            sum0 += p0 + p1; sum1 += p2 + p3;
            __nv_bfloat16 h0 = __float2bfloat16(p0), h1 = __float2bfloat16(p1);
            __nv_bfloat16 h2 = __float2bfloat16(p2), h3 = __float2bfloat16(p3);
            __nv_bfloat162 hi01 = __halves2bfloat162(h0, h1);
            __nv_bfloat162 hi23 = __halves2bfloat162(h2, h3);
            __nv_bfloat162 lo01 = __halves2bfloat162(
                __float2bfloat16(p0 - __bfloat162float(h0)),
                __float2bfloat16(p1 - __bfloat162float(h1)));
            __nv_bfloat162 lo23 = __halves2bfloat162(
                __float2bfloat16(p2 - __bfloat162float(h2)),
                __float2bfloat16(p3 - __bfloat162float(h3)));
            // frag j -> A-frag slot: kstep = j>>1, (j&1) selects k-lo/k-hi pair
            const int t4 = (j >> 1) * 4 + (j & 1) * 2;
            aph[t4 + 0] = *reinterpret_cast<uint32_t*>(&hi01);
            aph[t4 + 1] = *reinterpret_cast<uint32_t*>(&hi23);
            apl[t4 + 0] = *reinterpret_cast<uint32_t*>(&lo01);
            apl[t4 + 1] = *reinterpret_cast<uint32_t*>(&lo23);
        }
        sum0 += __shfl_xor_sync(0xffffffffu, sum0, 1);
        sum0 += __shfl_xor_sync(0xffffffffu, sum0, 2);
        sum1 += __shfl_xor_sync(0xffffffffu, sum1, 1);
        sum1 += __shfl_xor_sync(0xffffffffu, sum1, 2);
        l0 = l0 * corr0 + sum0;
        l1 = l1 * corr1 + sum1;
        #pragma unroll
        for (int j = 0; j < 8; j++) {
            o[j][0] *= corr0; o[j][1] *= corr0;
            o[j][2] *= corr1; o[j][3] *= corr1;
        }

        // ---- O += ph*vh + ph*vl + pl*vh   (K = 64 keys, N = 64 d)
        #pragma unroll
        for (int term = 0; term < 3; term++) {
            const uint32_t* ap = (term == 2) ? apl : aph;
            const uint32_t Vpl = kvb + 2*FTILEB + ((term == 1) ? FTILEB : 0);
            #pragma unroll
            for (int t = 0; t < 4; t++) {
                #pragma unroll
                for (int ns = 0; ns < 4; ns++) {
                    uint32_t b[4];
                    LDSM4T(b, Vpl + bVrow + (t*16) * FSTRIDE + ns * 32);
                    MMA16816(o[ns*2+0], ap + t*4, b[0], b[1]);
                    MMA16816(o[ns*2+1], ap + t*4, b[2], b[3]);
                }
            }
        }
    }

    // ---- epilogue: normalize + write triple (hi,hi,lo) to outA [4096 x 3072]
    const float inv0 = 1.0f / l0, inv1 = 1.0f / l1;
    const int r0 = qb + w*16 + (lane >> 2);
    const int gr0 = (bh >> 4) * SEQ + r0;
    const int colb = (bh & 15) * D_HEAD + 2 * (lane & 3);
    #pragma unroll
    for (int j = 0; j < 8; j++) {
        const int col = colb + j * 8;
        float v00 = o[j][0] * inv0, v01 = o[j][1] * inv0;
        float v10 = o[j][2] * inv1, v11 = o[j][3] * inv1;
        __nv_bfloat162 h0, l0b, h1, l1b;
        h0.x = __float2bfloat16(v00); h0.y = __float2bfloat16(v01);
        l0b.x = __float2bfloat16(v00 - __bfloat162float(h0.x));
        l0b.y = __float2bfloat16(v01 - __bfloat162float(h0.y));
        h1.x = __float2bfloat16(v10); h1.y = __float2bfloat16(v11);
        l1b.x = __float2bfloat16(v10 - __bfloat162float(h1.x));
        l1b.y = __float2bfloat16(v11 - __bfloat162float(h1.y));
        const size_t b0 = (size_t)gr0 * K3_DM + col;
        const size_t b1 = (size_t)(gr0 + 8) * K3_DM + col;
        *reinterpret_cast<__nv_bfloat162*>(outA + b0)               = h0;
        *reinterpret_cast<__nv_bfloat162*>(outA + b0 + D_MODEL)     = h0;
        *reinterpret_cast<__nv_bfloat162*>(outA + b0 + 2*D_MODEL)   = l0b;
        *reinterpret_cast<__nv_bfloat162*>(outA + b1)               = h1;
        *reinterpret_cast<__nv_bfloat162*>(outA + b1 + D_MODEL)     = h1;
        *reinterpret_cast<__nv_bfloat162*>(outA + b1 + 2*D_MODEL)   = l1b;
    }
}

// ---------------- launch --------------------------------------------------
extern "C" void kernel_launch(void* const* d_in, const int* in_sizes, int n_in,
                              void* d_out, int out_size)
{
    const float* x    = (const float*)d_in[0];
    const float* wq   = (const float*)d_in[1];
    const float* wk   = (const float*)d_in[2];
    const float* wv   = (const float*)d_in[3];
    const float* wo   = (const float*)d_in[4];
    const float* w1   = (const float*)d_in[5];
    const float* b1   = (const float*)d_in[6];
    const float* w2   = (const float*)d_in[7];
    const float* b2   = (const float*)d_in[8];
    const float* ln1g = (const float*)d_in[9];
    const float* ln1b = (const float*)d_in[10];
    const float* ln2g = (const float*)d_in[11];
    const float* ln2b = (const float*)d_in[12];
    float* out = (float*)d_out;

    __nv_bfloat16 *hA, *h2A, *atA, *ffA, *Bq, *Bk, *Bv, *Bo, *B1, *B2;
    __nv_bfloat16 *qh, *ql, *kh, *kl, *vh, *vl;
    float *x1;
    cudaGetSymbolAddress((void**)&hA,  g_hA);
    cudaGetSymbolAddress((void**)&h2A, g_h2A);
    cudaGetSymbolAddress((void**)&atA, g_atA);
    cudaGetSymbolAddress((void**)&ffA, g_ffA);
    cudaGetSymbolAddress((void**)&Bq,  g_Bq);
    cudaGetSymbolAddress((void**)&Bk,  g_Bk);
    cudaGetSymbolAddress((void**)&Bv,  g_Bv);
    cudaGetSymbolAddress((void**)&Bo,  g_Bo);
    cudaGetSymbolAddress((void**)&B1,  g_B1);
    cudaGetSymbolAddress((void**)&B2,  g_B2);
    cudaGetSymbolAddress((void**)&qh,  g_qh);
    cudaGetSymbolAddress((void**)&ql,  g_ql);
    cudaGetSymbolAddress((void**)&kh,  g_kh);
    cudaGetSymbolAddress((void**)&kl,  g_kl);
    cudaGetSymbolAddress((void**)&vh,  g_vh);
    cudaGetSymbolAddress((void**)&vl,  g_vl);
    cudaGetSymbolAddress((void**)&x1,  g_x1);

    cudaFuncSetAttribute(hmma_gemm<1>, cudaFuncAttributeMaxDynamicSharedMemorySize, SMEM_GEMM_BYTES);
    cudaFuncSetAttribute(hmma_gemm<2>, cudaFuncAttributeMaxDynamicSharedMemorySize, SMEM_GEMM_BYTES);
    cudaFuncSetAttribute(hmma_gemm<3>, cudaFuncAttributeMaxDynamicSharedMemorySize, SMEM_GEMM_BYTES);
    cudaFuncSetAttribute(hmma_gemm<4>, cudaFuncAttributeMaxDynamicSharedMemorySize, SMEM_GEMM_BYTES);
    cudaFuncSetAttribute(flash_mma,    cudaFuncAttributeMaxDynamicSharedMemorySize, SMEM_FLASH_BYTES);

    const dim3 blk(256);
    const dim3 gP (D_MODEL/BN, NROWS/BM);    // (8, 32)
    const dim3 gF1(D_FF/BN,    NROWS/BM);    // (32, 32)
    const dim3 gAttn(SEQ/64, BATCH*N_HEADS); // (32, 32)

    // Order chosen so launch #6 (ncu -s 5 -c 1) is a hmma_gemm.
    conv_triple_b<<<(D_MODEL*D_MODEL/4+255)/256, blk>>>(wq, Bq, D_MODEL, D_MODEL*D_MODEL); // 1
    conv_triple_b<<<(D_MODEL*D_MODEL/4+255)/256, blk>>>(wk, Bk, D_MODEL, D_MODEL*D_MODEL); // 2
    conv_triple_b<<<(D_MODEL*D_MODEL/4+255)/256, blk>>>(wv, Bv, D_MODEL, D_MODEL*D_MODEL); // 3
    ln_triple<<<NROWS, blk>>>(x, ln1g, ln1b, hA);                                          // 4
    hmma_gemm<4><<<gP, blk, SMEM_GEMM_BYTES>>>(hA, Bq, nullptr, nullptr, nullptr, qh, ql, 0.125f, D_MODEL, K3_DM); // 5
    hmma_gemm<4><<<gP, blk, SMEM_GEMM_BYTES>>>(hA, Bk, nullptr, nullptr, nullptr, kh, kl, 1.0f,   D_MODEL, K3_DM); // 6 <- profiled
    hmma_gemm<4><<<gP, blk, SMEM_GEMM_BYTES>>>(hA, Bv, nullptr, nullptr, nullptr, vh, vl, 1.0f,   D_MODEL, K3_DM); // 7
    conv_triple_b<<<(D_MODEL*D_MODEL/4+255)/256, blk>>>(wo, Bo, D_MODEL, D_MODEL*D_MODEL); // 8
    conv_triple_b<<<(D_FF*D_MODEL/4+255)/256,    blk>>>(w1, B1, D_MODEL, D_FF*D_MODEL);    // 9
    conv_triple_b<<<(D_MODEL*D_FF/4+255)/256,    blk>>>(w2, B2, D_FF,    D_MODEL*D_FF);    // 10
    flash_mma<<<gAttn, dim3(128), SMEM_FLASH_BYTES>>>(qh, ql, kh, kl, vh, vl, atA);        // 11
    hmma_gemm<1><<<gP, blk, SMEM_GEMM_BYTES>>>(atA, Bo, nullptr, x, x1, nullptr, nullptr, 1.0f, D_MODEL, K3_DM);   // 12
    ln_triple<<<NROWS, blk>>>(x1, ln2g, ln2b, h2A);                                        // 13
    hmma_gemm<2><<<gF1, blk, SMEM_GEMM_BYTES>>>(h2A, B1, b1, nullptr, nullptr, ffA, nullptr, 1.0f, D_FF, K3_DM);   // 14
    hmma_gemm<3><<<gP, blk, SMEM_GEMM_BYTES>>>(ffA, B2, b2, x1, out, nullptr, nullptr, 1.0f, D_MODEL, K3_FF);      // 15
}

// round 6
// speedup vs baseline: 2.7408x; 1.0889x over previous
#include <cuda_runtime.h>
#include <cuda_bf16.h>
#include <math.h>
#include <cstdint>

#define D_MODEL 1024
#define D_FF    4096
#define N_HEADS 16
#define D_HEAD  64
#define BATCH   2
#define SEQ     2048
#define NROWS   (BATCH*SEQ)   /* 4096 */

// ---------------- scratch (device globals; no allocation allowed) ----------
// two-plane (hi, lo) bf16 storage everywhere
__device__ __nv_bfloat16 g_hH  [NROWS * D_MODEL];
__device__ __nv_bfloat16 g_hL  [NROWS * D_MODEL];
__device__ __nv_bfloat16 g_h2H [NROWS * D_MODEL];
__device__ __nv_bfloat16 g_h2L [NROWS * D_MODEL];
__device__ __nv_bfloat16 g_atH [NROWS * D_MODEL];
__device__ __nv_bfloat16 g_atL [NROWS * D_MODEL];
__device__ __nv_bfloat16 g_ffH [NROWS * D_FF];
__device__ __nv_bfloat16 g_ffL [NROWS * D_FF];
__device__ __nv_bfloat16 g_BqH [D_MODEL * D_MODEL];
__device__ __nv_bfloat16 g_BqL [D_MODEL * D_MODEL];
__device__ __nv_bfloat16 g_BkH [D_MODEL * D_MODEL];
__device__ __nv_bfloat16 g_BkL [D_MODEL * D_MODEL];
__device__ __nv_bfloat16 g_BvH [D_MODEL * D_MODEL];
__device__ __nv_bfloat16 g_BvL [D_MODEL * D_MODEL];
__device__ __nv_bfloat16 g_BoH [D_MODEL * D_MODEL];
__device__ __nv_bfloat16 g_BoL [D_MODEL * D_MODEL];
__device__ __nv_bfloat16 g_B1H [D_FF * D_MODEL];
__device__ __nv_bfloat16 g_B1L [D_FF * D_MODEL];
__device__ __nv_bfloat16 g_B2H [D_MODEL * D_FF];
__device__ __nv_bfloat16 g_B2L [D_MODEL * D_FF];
__device__ __nv_bfloat16 g_qh [NROWS * D_MODEL];
__device__ __nv_bfloat16 g_ql [NROWS * D_MODEL];
__device__ __nv_bfloat16 g_kh [NROWS * D_MODEL];
__device__ __nv_bfloat16 g_kl [NROWS * D_MODEL];
__device__ __nv_bfloat16 g_vh [NROWS * D_MODEL];
__device__ __nv_bfloat16 g_vl [NROWS * D_MODEL];
__device__ float g_x1 [NROWS * D_MODEL];

// ================= PTX helpers =============================================
__device__ __forceinline__ uint32_t smem_u32(const void* p) {
    uint32_t a;
    asm("{ .reg .u64 t; cvta.to.shared.u64 t, %1; cvt.u32.u64 %0, t; }" : "=r"(a) : "l"(p));
    return a;
}
__device__ __forceinline__ void cp16(uint32_t s, const void* g) {
    asm volatile("cp.async.cg.shared.global [%0], [%1], 16;" :: "r"(s), "l"(g));
}
#define CP_COMMIT() asm volatile("cp.async.commit_group;" ::: "memory")
#define CP_WAIT(n)  asm volatile("cp.async.wait_group %0;" :: "n"(n) : "memory")

#define LDSM4(r, a) \
    asm volatile("ldmatrix.sync.aligned.m8n8.x4.shared.b16 {%0,%1,%2,%3}, [%4];" \
        : "=r"((r)[0]), "=r"((r)[1]), "=r"((r)[2]), "=r"((r)[3]) : "r"(a))
#define LDSM4T(r, a) \
    asm volatile("ldmatrix.sync.aligned.m8n8.x4.trans.shared.b16 {%0,%1,%2,%3}, [%4];" \
        : "=r"((r)[0]), "=r"((r)[1]), "=r"((r)[2]), "=r"((r)[3]) : "r"(a))

#define MMA16816(c, a, b0, b1) \
    asm volatile("mma.sync.aligned.m16n8k16.row.col.f32.bf16.bf16.f32 " \
        "{%0,%1,%2,%3}, {%4,%5,%6,%7}, {%8,%9}, {%0,%1,%2,%3};" \
        : "+f"((c)[0]), "+f"((c)[1]), "+f"((c)[2]), "+f"((c)[3]) \
        : "r"((a)[0]), "r"((a)[1]), "r"((a)[2]), "r"((a)[3]), "r"(b0), "r"(b1))

// ---------------- GEMM tiling: BM=BN=128, BK=64, 3 stages ------------------
#define BM 128
#define BN 128
#define BK 64
#define STAGES 3
#define GSTRIDE 144                        /* bytes per smem row (72 bf16) */
#define GTILEB (BM * GSTRIDE)              /* 18432 */
#define GSTAGEB (2 * GTILEB)               /* 36864 */
#define SMEM_GEMM_BYTES (STAGES * GSTAGEB) /* 110592 */

__device__ __forceinline__ float gelu_exact(float v) {
    return 0.5f * v * (1.0f + erff(v * 0.70710678118654752f));
}

// ======= HMMA GEMM: C[M,N] = (Ah+Al)[M,K] * (Bh+Bl)[N,K]^T, 3-term split ===
// logical K' = 3K via plane phases: A: (Ah,Ah,Al), B: (Bh,Bl,Bh)
// EPI: 1 +res->fp32, 2 gelu(+bias)->planes, 3 +bias+res->fp32, 4 scale->planes
template<int EPI>
__global__ __launch_bounds__(256, 2) void hmma_gemm(
    const __nv_bfloat16* __restrict__ Ah, const __nv_bfloat16* __restrict__ Al,
    const __nv_bfloat16* __restrict__ Bh, const __nv_bfloat16* __restrict__ Bl,
    const float* __restrict__ bias,
    const float* __restrict__ res,
    float* __restrict__ C,
    __nv_bfloat16* __restrict__ CH,
    __nv_bfloat16* __restrict__ CL,
    float scale,
    int N, int K, int kPerTerm)
{
    extern __shared__ char smem[];
    const uint32_t sbase = smem_u32(smem);
    const int tid  = threadIdx.x;
    const int wid  = tid >> 5, lane = tid & 31;
    const int wm   = wid >> 2, wn = wid & 3;       // 2 x 4 warp grid
    const int rowB = blockIdx.y * BM, colB = blockIdx.x * BN;

    auto load_stage = [&](int s, int kt) {
        const __nv_bfloat16* Ap = (kt >= 2*kPerTerm) ? Al : Ah;
        const __nv_bfloat16* Bp = (kt >= kPerTerm && kt < 2*kPerTerm) ? Bl : Bh;
        const int kph = (kt >= 2*kPerTerm) ? kt - 2*kPerTerm
                       : (kt >= kPerTerm ? kt - kPerTerm : kt);
        const int k0 = kph * BK;
        const uint32_t sA = sbase + s * GSTAGEB;
        const uint32_t sB = sA + GTILEB;
        const __nv_bfloat16* Ag = Ap + (size_t)rowB * K + k0;
        const __nv_bfloat16* Bg = Bp + (size_t)colB * K + k0;
        #pragma unroll
        for (int i = 0; i < 4; i++) {
            const int c = i * 256 + tid;          // 1024 chunks: 128 rows x 8
            const int r = c >> 3, seg = c & 7;
            cp16(sA + r * GSTRIDE + seg * 16, Ag + (size_t)r * K + seg * 8);
        }
        #pragma unroll
        for (int i = 0; i < 4; i++) {
            const int c = i * 256 + tid;
            const int r = c >> 3, seg = c & 7;
            cp16(sB + r * GSTRIDE + seg * 16, Bg + (size_t)r * K + seg * 8);
        }
        CP_COMMIT();
    };

    float acc[4][4][4];
    #pragma unroll
    for (int i = 0; i < 4; i++)
        #pragma unroll
        for (int j = 0; j < 4; j++)
            #pragma unroll
            for (int q = 0; q < 4; q++) acc[i][j][q] = 0.0f;

    const int niter = 3 * kPerTerm;
    load_stage(0, 0);
    load_stage(1, 1);

    for (int t = 0; t < niter; t++) {
        CP_WAIT(1);
        __syncthreads();
        if (t + 2 < niter) load_stage((t + 2) % STAGES, t + 2);

        const uint32_t sA = sbase + (t % STAGES) * GSTAGEB;
        const uint32_t sB = sA + GTILEB;
        #pragma unroll
        for (int ks = 0; ks < 4; ks++) {
            uint32_t a[4][4], b[2][4];
            #pragma unroll
            for (int mi = 0; mi < 4; mi++) {
                const uint32_t addr = sA
                    + (wm*64 + mi*16 + (lane & 15)) * GSTRIDE
                    + (ks*16 + (lane >> 4) * 8) * 2;
                LDSM4(a[mi], addr);
            }
            #pragma unroll
            for (int nt = 0; nt < 2; nt++) {
                const uint32_t addr = sB
                    + (wn*32 + nt*16 + (lane >> 4) * 8 + (lane & 7)) * GSTRIDE
                    + (ks*16 + ((lane >> 3) & 1) * 8) * 2;
                LDSM4(b[nt], addr);
            }
            #pragma unroll
            for (int mi = 0; mi < 4; mi++) {
                #pragma unroll
                for (int nt = 0; nt < 2; nt++) {
                    MMA16816(acc[mi][nt*2+0], a[mi], b[nt][0], b[nt][1]);
                    MMA16816(acc[mi][nt*2+1], a[mi], b[nt][2], b[nt][3]);
                }
            }
        }
        __syncthreads();
    }

    const int g  = lane >> 2;
    const int tq = lane & 3;
    #pragma unroll
    for (int mi = 0; mi < 4; mi++) {
        #pragma unroll
        for (int half = 0; half < 2; half++) {
            const int gr = rowB + wm*64 + mi*16 + g + half*8;
            #pragma unroll
            for (int ni = 0; ni < 4; ni++) {
                const int gc = colB + wn*32 + ni*8 + tq*2;
                float v0 = acc[mi][ni][half*2+0];
                float v1 = acc[mi][ni][half*2+1];
                if (EPI == 1) {
                    const float2 r2 = *reinterpret_cast<const float2*>(res + (size_t)gr * N + gc);
                    *reinterpret_cast<float2*>(C + (size_t)gr * N + gc) =
                        make_float2(v0 + r2.x, v1 + r2.y);
                } else if (EPI == 3) {
                    const float2 r2 = *reinterpret_cast<const float2*>(res + (size_t)gr * N + gc);
                    *reinterpret_cast<float2*>(C + (size_t)gr * N + gc) =
                        make_float2(v0 + bias[gc] + r2.x, v1 + bias[gc + 1] + r2.y);
                } else {
                    float s0, s1;
                    if (EPI == 2) {
                        s0 = gelu_exact(v0 + bias[gc]);
                        s1 = gelu_exact(v1 + bias[gc + 1]);
                    } else {           // EPI == 4
                        s0 = v0 * scale; s1 = v1 * scale;
                    }
                    __nv_bfloat162 hi2, lo2;
                    hi2.x = __float2bfloat16(s0);
                    hi2.y = __float2bfloat16(s1);
                    lo2.x = __float2bfloat16(s0 - __bfloat162float(hi2.x));
                    lo2.y = __float2bfloat16(s1 - __bfloat162float(hi2.y));
                    *reinterpret_cast<__nv_bfloat162*>(CH + (size_t)gr * N + gc) = hi2;
                    *reinterpret_cast<__nv_bfloat162*>(CL + (size_t)gr * N + gc) = lo2;
                }
            }
        }
    }
}

// ---------------- layernorm -> planes --------------------------------------
__global__ __launch_bounds__(256) void ln_planes(const float* __restrict__ x,
        const float* __restrict__ g, const float* __restrict__ b,
        __nv_bfloat16* __restrict__ H, __nv_bfloat16* __restrict__ L)
{
    __shared__ float red[256];
    const int row = blockIdx.x, t = threadIdx.x;
    const float4 v = reinterpret_cast<const float4*>(x + (size_t)row * D_MODEL)[t];
    red[t] = v.x + v.y + v.z + v.w;
    __syncthreads();
    #pragma unroll
    for (int o = 128; o > 0; o >>= 1) { if (t < o) red[t] += red[t + o]; __syncthreads(); }
    const float mu = red[0] * (1.0f / D_MODEL);
    __syncthreads();
    const float dx = v.x - mu, dy = v.y - mu, dz = v.z - mu, dw = v.w - mu;
    red[t] = dx*dx + dy*dy + dz*dz + dw*dw;
    __syncthreads();
    #pragma unroll
    for (int o = 128; o > 0; o >>= 1) { if (t < o) red[t] += red[t + o]; __syncthreads(); }
    const float rs = rsqrtf(red[0] * (1.0f / D_MODEL) + 1e-5f);
    const float4 gv = reinterpret_cast<const float4*>(g)[t];
    const float4 bv = reinterpret_cast<const float4*>(b)[t];
    float o4[4] = { dx*rs*gv.x + bv.x, dy*rs*gv.y + bv.y, dz*rs*gv.z + bv.z, dw*rs*gv.w + bv.w };
    __nv_bfloat16 h[4], l[4];
    #pragma unroll
    for (int j = 0; j < 4; j++) {
        h[j] = __float2bfloat16(o4[j]);
        l[j] = __float2bfloat16(o4[j] - __bfloat162float(h[j]));
    }
    const size_t base = (size_t)row * D_MODEL + t * 4;
    *reinterpret_cast<uint2*>(H + base) = *reinterpret_cast<uint2*>(h);
    *reinterpret_cast<uint2*>(L + base) = *reinterpret_cast<uint2*>(l);
}

// ---------------- fp32 -> planes converter ---------------------------------
__global__ __launch_bounds__(256) void conv_planes(const float* __restrict__ src,
        __nv_bfloat16* __restrict__ H, __nv_bfloat16* __restrict__ L, int total)
{
    const int i4 = blockIdx.x * 256 + threadIdx.x;
    if (i4 * 4 >= total) return;
    const float4 v = reinterpret_cast<const float4*>(src)[i4];
    float o4[4] = { v.x, v.y, v.z, v.w };
    __nv_bfloat16 h[4], l[4];
    #pragma unroll
    for (int j = 0; j < 4; j++) {
        h[j] = __float2bfloat16(o4[j]);
        l[j] = __float2bfloat16(o4[j] - __bfloat162float(h[j]));
    }
    *reinterpret_cast<uint2*>(H + (size_t)i4 * 4) = *reinterpret_cast<uint2*>(h);
    *reinterpret_cast<uint2*>(L + (size_t)i4 * 4) = *reinterpret_cast<uint2*>(l);
}

// ========== flash attention on tensor cores (BQ=64, TK=64, 4 warps) ========
#define FSTRIDE 144
#define FTILEB  (64 * FSTRIDE)         /* 9216 */
#define FQ_BYTES (2 * FTILEB)          /* 18432 */
#define FKV_BYTES (4 * FTILEB)         /* 36864 */
#define SMEM_FLASH_BYTES (FQ_BYTES + 2 * FKV_BYTES)  /* 92160 */

__global__ __launch_bounds__(128, 2) void flash_mma(
        const __nv_bfloat16* __restrict__ Qh, const __nv_bfloat16* __restrict__ Ql,
        const __nv_bfloat16* __restrict__ Kh, const __nv_bfloat16* __restrict__ Kl,
        const __nv_bfloat16* __restrict__ Vh, const __nv_bfloat16* __restrict__ Vl,
        __nv_bfloat16* __restrict__ outH, __nv_bfloat16* __restrict__ outL)
{
    extern __shared__ char smem[];
    const uint32_t sb = smem_u32(smem);
    const int tid = threadIdx.x;
    const int w = tid >> 5, lane = tid & 31;
    const int bh = blockIdx.y;                       // 0..31
    const size_t base = (size_t)(bh >> 4) * SEQ * D_MODEL + (size_t)(bh & 15) * D_HEAD;
    const int qb = blockIdx.x * 64;

    // ---- load Q tile (both planes) via cp.async
    #pragma unroll
    for (int i = 0; i < 4; i++) {
        const int c = i * 128 + tid;
        const int row = c >> 3, seg = c & 7;
        const size_t goff = base + (size_t)(qb + row) * D_MODEL + seg * 8;
        cp16(sb + 0      + row * FSTRIDE + seg * 16, Qh + goff);
        cp16(sb + FTILEB + row * FSTRIDE + seg * 16, Ql + goff);
    }
    auto load_kv = [&](int buf, int kt) {
        const uint32_t kvb = sb + FQ_BYTES + buf * FKV_BYTES;
        #pragma unroll
        for (int i = 0; i < 4; i++) {
            const int c = i * 128 + tid;
            const int row = c >> 3, seg = c & 7;
            const size_t goff = base + (size_t)(kt + row) * D_MODEL + seg * 8;
            const uint32_t soff = row * FSTRIDE + seg * 16;
            cp16(kvb + 0*FTILEB + soff, Kh + goff);
            cp16(kvb + 1*FTILEB + soff, Kl + goff);
            cp16(kvb + 2*FTILEB + soff, Vh + goff);
            cp16(kvb + 3*FTILEB + soff, Vl + goff);
        }
        CP_COMMIT();
    };
    load_kv(0, 0);

    float m0 = -1e30f, m1 = -1e30f, l0 = 0.0f, l1 = 0.0f;
    float o[8][4];
    #pragma unroll
    for (int j = 0; j < 8; j++)
        #pragma unroll
        for (int q = 0; q < 4; q++) o[j][q] = 0.0f;

    const uint32_t aQrow = (w*16 + (lane & 15)) * FSTRIDE + (lane >> 4) * 16;
    const uint32_t bKrow = ((lane >> 4) * 8 + (lane & 7)) * FSTRIDE + ((lane >> 3) & 1) * 16;
    const uint32_t bVrow = (lane & 15) * FSTRIDE + (lane >> 4) * 16;

    uint32_t qhf[4][4], qlf[4][4];     // Q fragments cached in registers

    for (int ti = 0; ti < SEQ / 64; ti++) {
        CP_WAIT(0);
        __syncthreads();
        if (ti + 1 < SEQ / 64) load_kv((ti + 1) & 1, (ti + 1) * 64);
        if (ti == 0) {
            #pragma unroll
            for (int ks = 0; ks < 4; ks++) {
                LDSM4(qhf[ks], sb + aQrow + ks * 32);
                LDSM4(qlf[ks], sb + FTILEB + aQrow + ks * 32);
            }
        }
        const uint32_t kvb = sb + FQ_BYTES + (ti & 1) * FKV_BYTES;

        // ---- S = qh*kh + qh*kl + ql*kh
        float s[8][4];
        #pragma unroll
        for (int j = 0; j < 8; j++)
            #pragma unroll
            for (int q = 0; q < 4; q++) s[j][q] = 0.0f;
        #pragma unroll
        for (int pass = 0; pass < 3; pass++) {
            const uint32_t Bpl = kvb + (pass == 1 ? FTILEB : 0);
            #pragma unroll
            for (int ks = 0; ks < 4; ks++) {
                const uint32_t* a = (pass == 2) ? qlf[ks] : qhf[ks];
                #pragma unroll
                for (int nt = 0; nt < 4; nt++) {
                    uint32_t b[4];
                    LDSM4(b, Bpl + bKrow + (nt*16) * FSTRIDE + ks * 32);
                    MMA16816(s[nt*2+0], a, b[0], b[1]);
                    MMA16816(s[nt*2+1], a, b[2], b[3]);
                }
            }
        }

        // ---- online softmax
        float mx0 = -1e30f, mx1 = -1e30f;
        #pragma unroll
        for (int j = 0; j < 8; j++) {
            mx0 = fmaxf(mx0, fmaxf(s[j][0], s[j][1]));
            mx1 = fmaxf(mx1, fmaxf(s[j][2], s[j][3]));
        }
        mx0 = fmaxf(mx0, __shfl_xor_sync(0xffffffffu, mx0, 1));
        mx0 = fmaxf(mx0, __shfl_xor_sync(0xffffffffu, mx0, 2));
        mx1 = fmaxf(mx1, __shfl_xor_sync(0xffffffffu, mx1, 1));
        mx1 = fmaxf(mx1, __shfl_xor_sync(0xffffffffu, mx1, 2));
        const float mn0 = fmaxf(m0, mx0), mn1 = fmaxf(m1, mx1);
        const float corr0 = __expf(m0 - mn0), corr1 = __expf(m1 - mn1);
        m0 = mn0; m1 = mn1;

        float sum0 = 0.0f, sum1 = 0.0f;
        uint32_t aph[16], apl[16];
        #pragma unroll
        for (int j = 0; j < 8; j++) {
            float p0 = __expf(s[j][0] - mn0), p1 = __expf(s[j][1] - mn0);
            float p2 = __expf(s[j][2] - mn1), p3 = __expf(s[j][3] - mn1);
            sum0 += p0 + p1; sum1 += p2 + p3;
            __nv_bfloat16 h0 = __float2bfloat16(p0), h1 = __float2bfloat16(p1);
            __nv_bfloat16 h2 = __float2bfloat16(p2), h3 = __float2bfloat16(p3);
            __nv_bfloat162 hi01 = __halves2bfloat162(h0, h1);
            __nv_bfloat162 hi23 = __halves2bfloat162(h2, h3);
            __nv_bfloat162 lo01 = __halves2bfloat162(
                __float2bfloat16(p0 - __bfloat162float(h0)),
                __float2bfloat16(p1 - __bfloat162float(h1)));
            __nv_bfloat162 lo23 = __halves2bfloat162(
                __float2bfloat16(p2 - __bfloat162float(h2)),
                __float2bfloat16(p3 - __bfloat162float(h3)));
            const int t4 = (j >> 1) * 4 + (j & 1) * 2;
            aph[t4 + 0] = *reinterpret_cast<uint32_t*>(&hi01);
            aph[t4 + 1] = *reinterpret_cast<uint32_t*>(&hi23);
            apl[t4 + 0] = *reinterpret_cast<uint32_t*>(&lo01);
            apl[t4 + 1] = *reinterpret_cast<uint32_t*>(&lo23);
        }
        sum0 += __shfl_xor_sync(0xffffffffu, sum0, 1);
        sum0 += __shfl_xor_sync(0xffffffffu, sum0, 2);
        sum1 += __shfl_xor_sync(0xffffffffu, sum1, 1);
        sum1 += __shfl_xor_sync(0xffffffffu, sum1, 2);
        l0 = l0 * corr0 + sum0;
        l1 = l1 * corr1 + sum1;
        #pragma unroll
        for (int j = 0; j < 8; j++) {
            o[j][0] *= corr0; o[j][1] *= corr0;
            o[j][2] *= corr1; o[j][3] *= corr1;
        }

        // ---- O += ph*vh + ph*vl + pl*vh
        #pragma unroll
        for (int term = 0; term < 3; term++) {
            const uint32_t* ap = (term == 2) ? apl : aph;
            const uint32_t Vpl = kvb + 2*FTILEB + ((term == 1) ? FTILEB : 0);
            #pragma unroll
            for (int t = 0; t < 4; t++) {
                #pragma unroll
                for (int ns = 0; ns < 4; ns++) {
                    uint32_t b[4];
                    LDSM4T(b, Vpl + bVrow + (t*16) * FSTRIDE + ns * 32);
                    MMA16816(o[ns*2+0], ap + t*4, b[0], b[1]);
                    MMA16816(o[ns*2+1], ap + t*4, b[2], b[3]);
                }
            }
        }
    }

    // ---- epilogue: normalize + write planes
    const float inv0 = 1.0f / l0, inv1 = 1.0f / l1;
    const int r0 = qb + w*16 + (lane >> 2);
    const int gr0 = (bh >> 4) * SEQ + r0;
    const int colb = (bh & 15) * D_HEAD + 2 * (lane & 3);
    #pragma unroll
    for (int j = 0; j < 8; j++) {
        const int col = colb + j * 8;
        float v00 = o[j][0] * inv0, v01 = o[j][1] * inv0;
        float v10 = o[j][2] * inv1, v11 = o[j][3] * inv1;
        __nv_bfloat162 h0, l0b, h1, l1b;
        h0.x = __float2bfloat16(v00); h0.y = __float2bfloat16(v01);
        l0b.x = __float2bfloat16(v00 - __bfloat162float(h0.x));
        l0b.y = __float2bfloat16(v01 - __bfloat162float(h0.y));
        h1.x = __float2bfloat16(v10); h1.y = __float2bfloat16(v11);
        l1b.x = __float2bfloat16(v10 - __bfloat162float(h1.x));
        l1b.y = __float2bfloat16(v11 - __bfloat162float(h1.y));
        const size_t b0 = (size_t)gr0 * D_MODEL + col;
        const size_t b1 = (size_t)(gr0 + 8) * D_MODEL + col;
        *reinterpret_cast<__nv_bfloat162*>(outH + b0) = h0;
        *reinterpret_cast<__nv_bfloat162*>(outL + b0) = l0b;
        *reinterpret_cast<__nv_bfloat162*>(outH + b1) = h1;
        *reinterpret_cast<__nv_bfloat162*>(outL + b1) = l1b;
    }
}

// ---------------- launch --------------------------------------------------
extern "C" void kernel_launch(void* const* d_in, const int* in_sizes, int n_in,
                              void* d_out, int out_size)
{
    const float* x    = (const float*)d_in[0];
    const float* wq   = (const float*)d_in[1];
    const float* wk   = (const float*)d_in[2];
    const float* wv   = (const float*)d_in[3];
    const float* wo   = (const float*)d_in[4];
    const float* w1   = (const float*)d_in[5];
    const float* b1   = (const float*)d_in[6];
    const float* w2   = (const float*)d_in[7];
    const float* b2   = (const float*)d_in[8];
    const float* ln1g = (const float*)d_in[9];
    const float* ln1b = (const float*)d_in[10];
    const float* ln2g = (const float*)d_in[11];
    const float* ln2b = (const float*)d_in[12];
    float* out = (float*)d_out;

    __nv_bfloat16 *hH,*hL,*h2H,*h2L,*atH,*atL,*ffH,*ffL;
    __nv_bfloat16 *BqH,*BqL,*BkH,*BkL,*BvH,*BvL,*BoH,*BoL,*B1H,*B1L,*B2H,*B2L;
    __nv_bfloat16 *qh,*ql,*kh,*kl,*vh,*vl;
    float *x1;
    cudaGetSymbolAddress((void**)&hH,  g_hH);   cudaGetSymbolAddress((void**)&hL,  g_hL);
    cudaGetSymbolAddress((void**)&h2H, g_h2H);  cudaGetSymbolAddress((void**)&h2L, g_h2L);
    cudaGetSymbolAddress((void**)&atH, g_atH);  cudaGetSymbolAddress((void**)&atL, g_atL);
    cudaGetSymbolAddress((void**)&ffH, g_ffH);  cudaGetSymbolAddress((void**)&ffL, g_ffL);
    cudaGetSymbolAddress((void**)&BqH, g_BqH);  cudaGetSymbolAddress((void**)&BqL, g_BqL);
    cudaGetSymbolAddress((void**)&BkH, g_BkH);  cudaGetSymbolAddress((void**)&BkL, g_BkL);
    cudaGetSymbolAddress((void**)&BvH, g_BvH);  cudaGetSymbolAddress((void**)&BvL, g_BvL);
    cudaGetSymbolAddress((void**)&BoH, g_BoH);  cudaGetSymbolAddress((void**)&BoL, g_BoL);
    cudaGetSymbolAddress((void**)&B1H, g_B1H);  cudaGetSymbolAddress((void**)&B1L, g_B1L);
    cudaGetSymbolAddress((void**)&B2H, g_B2H);  cudaGetSymbolAddress((void**)&B2L, g_B2L);
    cudaGetSymbolAddress((void**)&qh,  g_qh);   cudaGetSymbolAddress((void**)&ql,  g_ql);
    cudaGetSymbolAddress((void**)&kh,  g_kh);   cudaGetSymbolAddress((void**)&kl,  g_kl);
    cudaGetSymbolAddress((void**)&vh,  g_vh);   cudaGetSymbolAddress((void**)&vl,  g_vl);
    cudaGetSymbolAddress((void**)&x1,  g_x1);

    cudaFuncSetAttribute(hmma_gemm<1>, cudaFuncAttributeMaxDynamicSharedMemorySize, SMEM_GEMM_BYTES);
    cudaFuncSetAttribute(hmma_gemm<2>, cudaFuncAttributeMaxDynamicSharedMemorySize, SMEM_GEMM_BYTES);
    cudaFuncSetAttribute(hmma_gemm<3>, cudaFuncAttributeMaxDynamicSharedMemorySize, SMEM_GEMM_BYTES);
    cudaFuncSetAttribute(hmma_gemm<4>, cudaFuncAttributeMaxDynamicSharedMemorySize, SMEM_GEMM_BYTES);
    cudaFuncSetAttribute(flash_mma,    cudaFuncAttributeMaxDynamicSharedMemorySize, SMEM_FLASH_BYTES);

    const dim3 blk(256);
    const dim3 gP (D_MODEL/BN, NROWS/BM);    // (8, 32)
    const dim3 gF1(D_FF/BN,    NROWS/BM);    // (32, 32)
    const dim3 gAttn(SEQ/64, BATCH*N_HEADS); // (32, 32)
    const int kDM = D_MODEL / BK;            // 16
    const int kFF = D_FF / BK;               // 64

    ln_planes<<<NROWS, blk>>>(x, ln1g, ln1b, hH, hL);                                        // 1
    conv_planes<<<(D_MODEL*D_MODEL/4+255)/256, blk>>>(wq, BqH, BqL, D_MODEL*D_MODEL);        // 2
    conv_planes<<<(D_MODEL*D_MODEL/4+255)/256, blk>>>(wk, BkH, BkL, D_MODEL*D_MODEL);        // 3
    hmma_gemm<4><<<gP, blk, SMEM_GEMM_BYTES>>>(hH, hL, BqH, BqL, nullptr, nullptr, nullptr,
                                               qh, ql, 0.125f, D_MODEL, D_MODEL, kDM);       // 4 <- profiled
    conv_planes<<<(D_MODEL*D_MODEL/4+255)/256, blk>>>(wv, BvH, BvL, D_MODEL*D_MODEL);        // 5
    hmma_gemm<4><<<gP, blk, SMEM_GEMM_BYTES>>>(hH, hL, BkH, BkL, nullptr, nullptr, nullptr,
                                               kh, kl, 1.0f, D_MODEL, D_MODEL, kDM);         // 6
    hmma_gemm<4><<<gP, blk, SMEM_GEMM_BYTES>>>(hH, hL, BvH, BvL, nullptr, nullptr, nullptr,
                                               vh, vl, 1.0f, D_MODEL, D_MODEL, kDM);         // 7
    conv_planes<<<(D_MODEL*D_MODEL/4+255)/256, blk>>>(wo, BoH, BoL, D_MODEL*D_MODEL);        // 8
    conv_planes<<<(D_FF*D_MODEL/4+255)/256,    blk>>>(w1, B1H, B1L, D_FF*D_MODEL);           // 9
    conv_planes<<<(D_MODEL*D_FF/4+255)/256,    blk>>>(w2, B2H, B2L, D_MODEL*D_FF);           // 10
    flash_mma<<<gAttn, dim3(128), SMEM_FLASH_BYTES>>>(qh, ql, kh, kl, vh, vl, atH, atL);     // 11
    hmma_gemm<1><<<gP, blk, SMEM_GEMM_BYTES>>>(atH, atL, BoH, BoL, nullptr, x, x1,
                                               nullptr, nullptr, 1.0f, D_MODEL, D_MODEL, kDM); // 12
    ln_planes<<<NROWS, blk>>>(x1, ln2g, ln2b, h2H, h2L);                                     // 13
    hmma_gemm<2><<<gF1, blk, SMEM_GEMM_BYTES>>>(h2H, h2L, B1H, B1L, b1, nullptr, nullptr,
                                               ffH, ffL, 1.0f, D_FF, D_MODEL, kDM);          // 14
    hmma_gemm<3><<<gP, blk, SMEM_GEMM_BYTES>>>(ffH, ffL, B2H, B2L, b2, x1, out,
                                               nullptr, nullptr, 1.0f, D_MODEL, D_FF, kFF);  // 15
}